// round 1
// baseline (speedup 1.0000x reference)
#include <cuda_runtime.h>

// ---------------- constants ----------------
#define NB    2
#define CIN   64
#define CD    32
#define TT    8
#define HHd   24
#define WWd   24
#define NP    4608          // TT*HHd*WWd
#define TF    16
#define HF    48
#define WF    48
#define NTOT  (32*NP)       // groupnorm element count per (attn,b)

// ---------------- scratch (device globals; no allocation) ----------------
__device__ float g_xr [NB*CIN*NP];
__device__ float g_xcr[NB*CIN*NP];
__device__ float g_xd [NB*CD*NP];
__device__ float g_xcd[NB*CD*NP];
__device__ float g_q  [NB*16*NP];
__device__ float g_k  [NB*16*NP];
__device__ float g_v  [NB*32*NP];
__device__ float g_qsa[NB*16*NP];
__device__ float g_ksa[NB*16*NP];
__device__ float g_vsa[NB*32*NP];
__device__ float g_ao [2][NB*32*NP];   // attention outputs (cross, self)
__device__ float g_up [2][NB*64*NP];   // after GN + up conv, before upsample
__device__ float g_stats[8];           // (attn*2+b)*2 = {mean, rstd}

// ---------------- f32x2 packed helpers ----------------
typedef unsigned long long u64;
__device__ __forceinline__ u64 pk2(float lo, float hi) {
    u64 r; asm("mov.b64 %0, {%1, %2};" : "=l"(r) : "f"(lo), "f"(hi)); return r;
}
__device__ __forceinline__ void up2(u64 v, float& lo, float& hi) {
    asm("mov.b64 {%0, %1}, %2;" : "=f"(lo), "=f"(hi) : "l"(v));
}
__device__ __forceinline__ u64 ffma2(u64 a, u64 b, u64 c) {
    u64 d; asm("fma.rn.f32x2 %0, %1, %2, %3;" : "=l"(d) : "l"(a), "l"(b), "l"(c)); return d;
}
__device__ __forceinline__ u64 fmul2(u64 a, u64 b) {
    u64 d; asm("mul.rn.f32x2 %0, %1, %2;" : "=l"(d) : "l"(a), "l"(b)); return d;
}
__device__ __forceinline__ u64 fadd2(u64 a, u64 b) {
    u64 d; asm("add.rn.f32x2 %0, %1, %2;" : "=l"(d) : "l"(a), "l"(b)); return d;
}

// ---------------- K1: trilinear downsample (16,48,48)->(8,24,24) ----------------
__global__ void k_resize(const float* __restrict__ x, const float* __restrict__ xc) {
    int i = blockIdx.x * 256 + threadIdx.x;            // < NB*CIN*NP
    const float* src = blockIdx.z ? xc : x;
    float* dst = blockIdx.z ? g_xcr : g_xr;
    int p  = i % NP;
    int bc = i / NP;
    int w = p % WWd, h = (p / WWd) % HHd, t = p / (WWd * HHd);

    float pt = (float)t * (15.0f / 7.0f);
    int t0 = (int)pt; float wt = pt - (float)t0; int t1 = min(t0 + 1, 15); t0 = min(t0, 15);
    float ph = (float)h * (47.0f / 23.0f);
    int h0 = (int)ph; float wh = ph - (float)h0; int h1 = min(h0 + 1, 47); h0 = min(h0, 47);
    float pw = (float)w * (47.0f / 23.0f);
    int w0 = (int)pw; float ww = pw - (float)w0; int w1 = min(w0 + 1, 47); w0 = min(w0, 47);

    const float* base = src + (size_t)bc * (TF * HF * WF);
#define ATI(ti,hi,wi) __ldg(base + (ti)*(HF*WF) + (hi)*WF + (wi))
    float c00 = ATI(t0,h0,w0); c00 += (ATI(t0,h0,w1) - c00) * ww;
    float c01 = ATI(t0,h1,w0); c01 += (ATI(t0,h1,w1) - c01) * ww;
    float c10 = ATI(t1,h0,w0); c10 += (ATI(t1,h0,w1) - c10) * ww;
    float c11 = ATI(t1,h1,w0); c11 += (ATI(t1,h1,w1) - c11) * ww;
#undef ATI
    float c0 = c00 + (c01 - c00) * wh;
    float c1 = c10 + (c11 - c10) * wh;
    dst[i] = c0 + (c1 - c0) * wt;
}

// ---------------- K2: down conv 64 -> 32 ----------------
__global__ __launch_bounds__(128) void k_down(
    const float* __restrict__ wd, const float* __restrict__ bd,
    const float* __restrict__ wdc, const float* __restrict__ bdc) {
    __shared__ float sw[CD * CIN];
    __shared__ float sb[CD];
    const float* w  = blockIdx.z ? wdc : wd;
    const float* bb = blockIdx.z ? bdc : bd;
    const float* in = blockIdx.z ? g_xcr : g_xr;
    float* out      = blockIdx.z ? g_xcd : g_xd;
    for (int i = threadIdx.x; i < CD * CIN; i += 128) sw[i] = w[i];
    if (threadIdx.x < CD) sb[threadIdx.x] = bb[threadIdx.x];
    __syncthreads();
    int idx = blockIdx.x * 128 + threadIdx.x;          // < NB*NP
    int b = idx / NP, p = idx % NP;
    float xin[CIN];
#pragma unroll
    for (int c = 0; c < CIN; c++) xin[c] = in[(b * CIN + c) * NP + p];
#pragma unroll
    for (int o = 0; o < CD; o++) {
        float acc = sb[o];
#pragma unroll
        for (int c = 0; c < CIN; c++) acc = fmaf(sw[o * CIN + c], xin[c], acc);
        out[(b * CD + o) * NP + p] = acc;
    }
}

// ---------------- K3: QKV projections + RoPE (scale folded into q) ----------------
__global__ __launch_bounds__(128) void k_proj(
    const float* __restrict__ wq,  const float* __restrict__ bq,
    const float* __restrict__ wk,  const float* __restrict__ bk,
    const float* __restrict__ wv,  const float* __restrict__ bv,
    const float* __restrict__ wqs, const float* __restrict__ bqs,
    const float* __restrict__ wks, const float* __restrict__ bks,
    const float* __restrict__ wvs, const float* __restrict__ bvs,
    const float* __restrict__ off, const float* __restrict__ offc) {
    __shared__ float s_wq[512], s_wk[512], s_wqs[512], s_wks[512];
    __shared__ float s_wv[1024], s_wvs[1024];
    __shared__ float s_bq[16], s_bk[16], s_bqs[16], s_bks[16], s_bv[32], s_bvs[32];
    for (int i = threadIdx.x; i < 512; i += 128) {
        s_wq[i] = wq[i]; s_wk[i] = wk[i]; s_wqs[i] = wqs[i]; s_wks[i] = wks[i];
    }
    for (int i = threadIdx.x; i < 1024; i += 128) { s_wv[i] = wv[i]; s_wvs[i] = wvs[i]; }
    if (threadIdx.x < 16) {
        s_bq[threadIdx.x] = bq[threadIdx.x]; s_bk[threadIdx.x] = bk[threadIdx.x];
        s_bqs[threadIdx.x] = bqs[threadIdx.x]; s_bks[threadIdx.x] = bks[threadIdx.x];
    }
    if (threadIdx.x < 32) { s_bv[threadIdx.x] = bv[threadIdx.x]; s_bvs[threadIdx.x] = bvs[threadIdx.x]; }
    __syncthreads();

    int idx = blockIdx.x * 128 + threadIdx.x;          // < NB*NP
    int b = idx / NP, p = idx % NP, t = p / (HHd * WWd);

    float xd[32], xcd[32];
#pragma unroll
    for (int c = 0; c < 32; c++) {
        xd[c]  = g_xd [(b * 32 + c) * NP + p];
        xcd[c] = g_xcd[(b * 32 + c) * NP + p];
    }

    const float invf[8] = {1.0f, 0.31622776601683794f, 0.1f, 0.031622776601683794f,
                           0.01f, 0.0031622776601683794f, 0.001f, 0.00031622776601683794f};
    float se[8], ce[8], sc[8], cc[8];
    float tf = (float)t;
#pragma unroll
    for (int i = 0; i < 8; i++) {
        float a = tf * invf[i];
        float s = sinf(a), c = cosf(a);
        float o1 = off[i * 500 + t];
        float o2 = offc[i * 500 + t];
        se[i] = s + o1; ce[i] = c + o1;     // note: same offset added to sin AND cos
        sc[i] = s + o2; cc[i] = c + o2;
    }

    float tmp[16];
    // q = rope(Wq * xd + bq, se/ce), scaled by 0.5 (1/SCALE)
#pragma unroll
    for (int o = 0; o < 16; o++) {
        float acc = s_bq[o];
#pragma unroll
        for (int c = 0; c < 32; c++) acc = fmaf(s_wq[o * 32 + c], xd[c], acc);
        tmp[o] = acc;
    }
#pragma unroll
    for (int i = 0; i < 8; i++) {
        g_q[(b * 16 + i)     * NP + p] = 0.5f * (tmp[i] * ce[i] - tmp[8 + i] * se[i]);
        g_q[(b * 16 + 8 + i) * NP + p] = 0.5f * (tmp[8 + i] * ce[i] + tmp[i] * se[i]);
    }
    // k = rope(Wk * xcd + bk, sc/cc)
#pragma unroll
    for (int o = 0; o < 16; o++) {
        float acc = s_bk[o];
#pragma unroll
        for (int c = 0; c < 32; c++) acc = fmaf(s_wk[o * 32 + c], xcd[c], acc);
        tmp[o] = acc;
    }
#pragma unroll
    for (int i = 0; i < 8; i++) {
        g_k[(b * 16 + i)     * NP + p] = tmp[i] * cc[i] - tmp[8 + i] * sc[i];
        g_k[(b * 16 + 8 + i) * NP + p] = tmp[8 + i] * cc[i] + tmp[i] * sc[i];
    }
    // v
#pragma unroll
    for (int o = 0; o < 32; o++) {
        float acc = s_bv[o];
#pragma unroll
        for (int c = 0; c < 32; c++) acc = fmaf(s_wv[o * 32 + c], xcd[c], acc);
        g_v[(b * 32 + o) * NP + p] = acc;
    }
    // q_sa = rope(Wqs * xcd + bqs, se/ce) * 0.5
#pragma unroll
    for (int o = 0; o < 16; o++) {
        float acc = s_bqs[o];
#pragma unroll
        for (int c = 0; c < 32; c++) acc = fmaf(s_wqs[o * 32 + c], xcd[c], acc);
        tmp[o] = acc;
    }
#pragma unroll
    for (int i = 0; i < 8; i++) {
        g_qsa[(b * 16 + i)     * NP + p] = 0.5f * (tmp[i] * ce[i] - tmp[8 + i] * se[i]);
        g_qsa[(b * 16 + 8 + i) * NP + p] = 0.5f * (tmp[8 + i] * ce[i] + tmp[i] * se[i]);
    }
    // k_sa = rope(Wks * xcd + bks, se/ce)
#pragma unroll
    for (int o = 0; o < 16; o++) {
        float acc = s_bks[o];
#pragma unroll
        for (int c = 0; c < 32; c++) acc = fmaf(s_wks[o * 32 + c], xcd[c], acc);
        tmp[o] = acc;
    }
#pragma unroll
    for (int i = 0; i < 8; i++) {
        g_ksa[(b * 16 + i)     * NP + p] = tmp[i] * ce[i] - tmp[8 + i] * se[i];
        g_ksa[(b * 16 + 8 + i) * NP + p] = tmp[8 + i] * ce[i] + tmp[i] * se[i];
    }
    // v_sa
#pragma unroll
    for (int o = 0; o < 32; o++) {
        float acc = s_bvs[o];
#pragma unroll
        for (int c = 0; c < 32; c++) acc = fmaf(s_wvs[o * 32 + c], xcd[c], acc);
        g_vsa[(b * 32 + o) * NP + p] = acc;
    }
}

// ---------------- K4: flash attention (online softmax, f32x2 packed FMA) ----------------
__global__ __launch_bounds__(128) void k_attn() {
    const float *Q, *K, *V; float* O;
    if (blockIdx.z == 0) { Q = g_q;   K = g_k;   V = g_v;   O = g_ao[0]; }
    else                 { Q = g_qsa; K = g_ksa; V = g_vsa; O = g_ao[1]; }
    int b = blockIdx.y;
    Q += b * 16 * NP; K += b * 16 * NP; V += b * 32 * NP; O += b * 32 * NP;

    __shared__ __align__(16) float sK[128][20];   // 16 used, padded for alignment/banks
    __shared__ __align__(16) float sV[128][36];   // 32 used

    int tid = threadIdx.x;
    int qi = blockIdx.x * 128 + tid;

    u64 q2[8];
#pragma unroll
    for (int i = 0; i < 8; i++) q2[i] = pk2(Q[(2 * i) * NP + qi], Q[(2 * i + 1) * NP + qi]);

    u64 acc[16];
#pragma unroll
    for (int i = 0; i < 16; i++) acc[i] = pk2(0.0f, 0.0f);
    float m = -1e30f, l = 0.0f;

    for (int j0 = 0; j0 < NP; j0 += 128) {
        __syncthreads();
#pragma unroll
        for (int c = 0; c < 16; c++) sK[tid][c] = K[c * NP + j0 + tid];
#pragma unroll
        for (int c = 0; c < 32; c++) sV[tid][c] = V[c * NP + j0 + tid];
        __syncthreads();
#pragma unroll 4
        for (int j = 0; j < 128; j++) {
            const u64* kr = (const u64*)sK[j];
            u64 sa = fmul2(q2[0], kr[0]);
            u64 sb = fmul2(q2[1], kr[1]);
            sa = ffma2(q2[2], kr[2], sa);
            sb = ffma2(q2[3], kr[3], sb);
            sa = ffma2(q2[4], kr[4], sa);
            sb = ffma2(q2[5], kr[5], sb);
            sa = ffma2(q2[6], kr[6], sa);
            sb = ffma2(q2[7], kr[7], sb);
            sa = fadd2(sa, sb);
            float s0, s1; up2(sa, s0, s1);
            float s = s0 + s1;
            float p;
            if (s > m) {
                float corr = __expf(m - s);
                m = s;
                l *= corr;
                u64 c2 = pk2(corr, corr);
#pragma unroll
                for (int i = 0; i < 16; i++) acc[i] = fmul2(acc[i], c2);
                p = 1.0f;
            } else {
                p = __expf(s - m);
            }
            l += p;
            u64 p2 = pk2(p, p);
            const u64* vr = (const u64*)sV[j];
#pragma unroll
            for (int i = 0; i < 16; i++) acc[i] = ffma2(p2, vr[i], acc[i]);
        }
    }
    float inv = 1.0f / l;
#pragma unroll
    for (int i = 0; i < 16; i++) {
        float a0, a1; up2(acc[i], a0, a1);
        O[(2 * i)     * NP + qi] = a0 * inv;
        O[(2 * i + 1) * NP + qi] = a1 * inv;
    }
}

// ---------------- K5: groupnorm stats (per batch, over all 32*4608 elems) ----------------
__global__ void k_stats() {
    int gb = blockIdx.x;                  // attn*2 + b
    int a = gb >> 1, b = gb & 1;
    const float* src = g_ao[a] + b * 32 * NP;
    double s1 = 0.0, s2 = 0.0;
    for (int i = threadIdx.x; i < NTOT; i += 256) {
        float v = src[i];
        s1 += (double)v;
        s2 += (double)v * (double)v;
    }
    __shared__ double r1[256], r2[256];
    r1[threadIdx.x] = s1; r2[threadIdx.x] = s2;
    __syncthreads();
    for (int s = 128; s > 0; s >>= 1) {
        if (threadIdx.x < s) { r1[threadIdx.x] += r1[threadIdx.x + s]; r2[threadIdx.x] += r2[threadIdx.x + s]; }
        __syncthreads();
    }
    if (threadIdx.x == 0) {
        double mu = r1[0] / (double)NTOT;
        double var = r2[0] / (double)NTOT - mu * mu;
        g_stats[gb * 2]     = (float)mu;
        g_stats[gb * 2 + 1] = rsqrtf((float)var + 1e-5f);
    }
}

// ---------------- K6: groupnorm apply + up conv 32 -> 64 ----------------
__global__ __launch_bounds__(128) void k_gnup(
    const float* __restrict__ gnw,  const float* __restrict__ gnb,
    const float* __restrict__ gnws, const float* __restrict__ gnbs,
    const float* __restrict__ wup,  const float* __restrict__ bup,
    const float* __restrict__ wups, const float* __restrict__ bups) {
    int a = blockIdx.z, b = blockIdx.y;
    __shared__ float sw[64 * 32];
    __shared__ float sb2[64], sa_[32], sd_[32];
    const float* w   = a ? wups : wup;
    const float* bb  = a ? bups : bup;
    const float* gw  = a ? gnws : gnw;
    const float* gbb = a ? gnbs : gnb;
    float mu   = g_stats[(a * 2 + b) * 2];
    float rstd = g_stats[(a * 2 + b) * 2 + 1];
    for (int i = threadIdx.x; i < 2048; i += 128) sw[i] = w[i];
    if (threadIdx.x < 64) sb2[threadIdx.x] = bb[threadIdx.x];
    if (threadIdx.x < 32) {
        float aa = rstd * gw[threadIdx.x];
        sa_[threadIdx.x] = aa;
        sd_[threadIdx.x] = gbb[threadIdx.x] - mu * aa;
    }
    __syncthreads();
    int p = blockIdx.x * 128 + threadIdx.x;
    const float* src = g_ao[a] + b * 32 * NP;
    float xn[32];
#pragma unroll
    for (int c = 0; c < 32; c++) xn[c] = fmaf(src[c * NP + p], sa_[c], sd_[c]);
    float* dst = g_up[a] + b * 64 * NP;
#pragma unroll
    for (int o = 0; o < 64; o++) {
        float acc = sb2[o];
#pragma unroll
        for (int c = 0; c < 32; c++) acc = fmaf(sw[o * 32 + c], xn[c], acc);
        dst[o * NP + p] = acc;
    }
}

// ---------------- K7: upsample both branches + combine ----------------
__device__ __forceinline__ float tri8(const float* __restrict__ s,
                                      int p00, int p01, int p10, int p11,
                                      int w0, int w1, float ww, float wh, float wt) {
    float c00 = s[p00 + w0]; c00 += (s[p00 + w1] - c00) * ww;
    float c01 = s[p01 + w0]; c01 += (s[p01 + w1] - c01) * ww;
    float c10 = s[p10 + w0]; c10 += (s[p10 + w1] - c10) * ww;
    float c11 = s[p11 + w0]; c11 += (s[p11 + w1] - c11) * ww;
    float c0 = c00 + (c01 - c00) * wh;
    float c1 = c10 + (c11 - c10) * wh;
    return c0 + (c1 - c0) * wt;
}

__global__ void k_final(const float* __restrict__ xc, float* __restrict__ out) {
    int idx = blockIdx.x * 256 + threadIdx.x;          // < 2*64*16*48*48
    int w = idx % WF;
    int h = (idx / WF) % HF;
    int t = (idx / (WF * HF)) % TF;
    int bc = idx / (WF * HF * TF);                     // b*64 + c

    float pt = (float)t * (7.0f / 15.0f);
    int t0 = (int)pt; float wt = pt - (float)t0; int t1 = min(t0 + 1, 7); t0 = min(t0, 7);
    float ph = (float)h * (23.0f / 47.0f);
    int h0 = (int)ph; float wh = ph - (float)h0; int h1 = min(h0 + 1, 23); h0 = min(h0, 23);
    float pw = (float)w * (23.0f / 47.0f);
    int w0 = (int)pw; float ww = pw - (float)w0; int w1 = min(w0 + 1, 23); w0 = min(w0, 23);

    int base = bc * NP;
    int p00 = t0 * (HHd * WWd) + h0 * WWd;
    int p01 = t0 * (HHd * WWd) + h1 * WWd;
    int p10 = t1 * (HHd * WWd) + h0 * WWd;
    int p11 = t1 * (HHd * WWd) + h1 * WWd;

    float r_cross = tri8(g_up[0] + base, p00, p01, p10, p11, w0, w1, ww, wh, wt);
    float r_self  = tri8(g_up[1] + base, p00, p01, p10, p11, w0, w1, ww, wh, wt);
    out[idx] = r_self + xc[idx] - 0.5f * r_cross;
}

// ---------------- launch ----------------
extern "C" void kernel_launch(void* const* d_in, const int* in_sizes, int n_in,
                              void* d_out, int out_size) {
    const float* x       = (const float*)d_in[0];
    const float* x_c     = (const float*)d_in[1];
    const float* w_down  = (const float*)d_in[2];
    const float* b_down  = (const float*)d_in[3];
    const float* w_downc = (const float*)d_in[4];
    const float* b_downc = (const float*)d_in[5];
    const float* w_q     = (const float*)d_in[6];
    const float* b_q     = (const float*)d_in[7];
    const float* w_k     = (const float*)d_in[8];
    const float* b_k     = (const float*)d_in[9];
    const float* w_v     = (const float*)d_in[10];
    const float* b_v     = (const float*)d_in[11];
    const float* w_qsa   = (const float*)d_in[12];
    const float* b_qsa   = (const float*)d_in[13];
    const float* w_ksa   = (const float*)d_in[14];
    const float* b_ksa   = (const float*)d_in[15];
    const float* w_vsa   = (const float*)d_in[16];
    const float* b_vsa   = (const float*)d_in[17];
    const float* gn_w    = (const float*)d_in[18];
    const float* gn_b    = (const float*)d_in[19];
    const float* gn_wsa  = (const float*)d_in[20];
    const float* gn_bsa  = (const float*)d_in[21];
    const float* w_up    = (const float*)d_in[22];
    const float* b_up    = (const float*)d_in[23];
    const float* w_upsa  = (const float*)d_in[24];
    const float* b_upsa  = (const float*)d_in[25];
    const float* offset  = (const float*)d_in[26];
    const float* offsetc = (const float*)d_in[27];

    dim3 g1(2304, 1, 2);
    k_resize<<<g1, 256>>>(x, x_c);

    dim3 g2(72, 1, 2);
    k_down<<<g2, 128>>>(w_down, b_down, w_downc, b_downc);

    k_proj<<<72, 128>>>(w_q, b_q, w_k, b_k, w_v, b_v,
                        w_qsa, b_qsa, w_ksa, b_ksa, w_vsa, b_vsa,
                        offset, offsetc);

    dim3 g4(36, 2, 2);
    k_attn<<<g4, 128>>>();

    k_stats<<<4, 256>>>();

    dim3 g6(36, 2, 2);
    k_gnup<<<g6, 128>>>(gn_w, gn_b, gn_wsa, gn_bsa, w_up, b_up, w_upsa, b_upsa);

    k_final<<<18432, 256>>>(x_c, (float*)d_out);
}

// round 3
// speedup vs baseline: 1.7017x; 1.7017x over previous
#include <cuda_runtime.h>
#include <math_constants.h>

// ---------------- constants ----------------
#define NB    2
#define CIN   64
#define CD    32
#define TT    8
#define HHd   24
#define WWd   24
#define NP    4608          // TT*HHd*WWd
#define TF    16
#define HF    48
#define WF    48
#define NTOT  (32*NP)       // groupnorm element count per (attn,b)
#define SPLIT 4
#define KCH   (NP/SPLIT)    // 1152 keys per split

// ---------------- scratch (device globals; no allocation) ----------------
__device__ float g_xr [NB*CIN*NP];
__device__ float g_xcr[NB*CIN*NP];
__device__ float g_xd [NB*CD*NP];
__device__ float g_xcd[NB*CD*NP];
__device__ float g_q  [NB*16*NP];
__device__ float g_k  [NB*16*NP];
__device__ float g_v  [NB*32*NP];
__device__ float g_qsa[NB*16*NP];
__device__ float g_ksa[NB*16*NP];
__device__ float g_vsa[NB*32*NP];
__device__ float g_pacc[2*NB*SPLIT*32*NP];   // split-K partial acc
__device__ float g_pml [2*NB*SPLIT*2*NP];    // split-K partial m,l
__device__ float g_ao [2][NB*32*NP];         // attention outputs (cross, self)
__device__ float g_up [2][NB*64*NP];         // after GN + up conv, before upsample
__device__ double g_psum[4][8][2];           // GN partial sums [gb][chunk][s1,s2]

// ---------------- f32x2 packed helpers ----------------
typedef unsigned long long u64;
__device__ __forceinline__ u64 pk2(float lo, float hi) {
    u64 r; asm("mov.b64 %0, {%1, %2};" : "=l"(r) : "f"(lo), "f"(hi)); return r;
}
__device__ __forceinline__ void up2(u64 v, float& lo, float& hi) {
    asm("mov.b64 {%0, %1}, %2;" : "=f"(lo), "=f"(hi) : "l"(v));
}
__device__ __forceinline__ u64 ffma2(u64 a, u64 b, u64 c) {
    u64 d; asm("fma.rn.f32x2 %0, %1, %2, %3;" : "=l"(d) : "l"(a), "l"(b), "l"(c)); return d;
}
__device__ __forceinline__ u64 fmul2(u64 a, u64 b) {
    u64 d; asm("mul.rn.f32x2 %0, %1, %2;" : "=l"(d) : "l"(a), "l"(b)); return d;
}
__device__ __forceinline__ u64 fadd2(u64 a, u64 b) {
    u64 d; asm("add.rn.f32x2 %0, %1, %2;" : "=l"(d) : "l"(a), "l"(b)); return d;
}

// ---------------- K1: trilinear downsample (16,48,48)->(8,24,24) ----------------
__global__ void k_resize(const float* __restrict__ x, const float* __restrict__ xc) {
    int i = blockIdx.x * 256 + threadIdx.x;            // < NB*CIN*NP
    const float* src = blockIdx.z ? xc : x;
    float* dst = blockIdx.z ? g_xcr : g_xr;
    int p  = i % NP;
    int bc = i / NP;
    int w = p % WWd, h = (p / WWd) % HHd, t = p / (WWd * HHd);

    float pt = (float)t * (15.0f / 7.0f);
    int t0 = (int)pt; float wt = pt - (float)t0; int t1 = min(t0 + 1, 15); t0 = min(t0, 15);
    float ph = (float)h * (47.0f / 23.0f);
    int h0 = (int)ph; float wh = ph - (float)h0; int h1 = min(h0 + 1, 47); h0 = min(h0, 47);
    float pw = (float)w * (47.0f / 23.0f);
    int w0 = (int)pw; float ww = pw - (float)w0; int w1 = min(w0 + 1, 47); w0 = min(w0, 47);

    const float* base = src + (size_t)bc * (TF * HF * WF);
#define ATI(ti,hi,wi) __ldg(base + (ti)*(HF*WF) + (hi)*WF + (wi))
    float c00 = ATI(t0,h0,w0); c00 += (ATI(t0,h0,w1) - c00) * ww;
    float c01 = ATI(t0,h1,w0); c01 += (ATI(t0,h1,w1) - c01) * ww;
    float c10 = ATI(t1,h0,w0); c10 += (ATI(t1,h0,w1) - c10) * ww;
    float c11 = ATI(t1,h1,w0); c11 += (ATI(t1,h1,w1) - c11) * ww;
#undef ATI
    float c0 = c00 + (c01 - c00) * wh;
    float c1 = c10 + (c11 - c10) * wh;
    dst[i] = c0 + (c1 - c0) * wt;
}

// ---------------- K2: down conv 64 -> 32 ----------------
__global__ __launch_bounds__(128) void k_down(
    const float* __restrict__ wd, const float* __restrict__ bd,
    const float* __restrict__ wdc, const float* __restrict__ bdc) {
    __shared__ float sw[CD * CIN];
    __shared__ float sb[CD];
    const float* w  = blockIdx.z ? wdc : wd;
    const float* bb = blockIdx.z ? bdc : bd;
    const float* in = blockIdx.z ? g_xcr : g_xr;
    float* out      = blockIdx.z ? g_xcd : g_xd;
    for (int i = threadIdx.x; i < CD * CIN; i += 128) sw[i] = w[i];
    if (threadIdx.x < CD) sb[threadIdx.x] = bb[threadIdx.x];
    __syncthreads();
    int idx = blockIdx.x * 128 + threadIdx.x;          // < NB*NP
    int b = idx / NP, p = idx % NP;
    float xin[CIN];
#pragma unroll
    for (int c = 0; c < CIN; c++) xin[c] = in[(b * CIN + c) * NP + p];
#pragma unroll
    for (int o = 0; o < CD; o++) {
        float acc = sb[o];
#pragma unroll
        for (int c = 0; c < CIN; c++) acc = fmaf(sw[o * CIN + c], xin[c], acc);
        out[(b * CD + o) * NP + p] = acc;
    }
}

// ---------------- K3: QKV projections + RoPE (scale folded into q) ----------------
__global__ __launch_bounds__(128) void k_proj(
    const float* __restrict__ wq,  const float* __restrict__ bq,
    const float* __restrict__ wk,  const float* __restrict__ bk,
    const float* __restrict__ wv,  const float* __restrict__ bv,
    const float* __restrict__ wqs, const float* __restrict__ bqs,
    const float* __restrict__ wks, const float* __restrict__ bks,
    const float* __restrict__ wvs, const float* __restrict__ bvs,
    const float* __restrict__ off, const float* __restrict__ offc) {
    __shared__ float s_wq[512], s_wk[512], s_wqs[512], s_wks[512];
    __shared__ float s_wv[1024], s_wvs[1024];
    __shared__ float s_bq[16], s_bk[16], s_bqs[16], s_bks[16], s_bv[32], s_bvs[32];
    for (int i = threadIdx.x; i < 512; i += 128) {
        s_wq[i] = wq[i]; s_wk[i] = wk[i]; s_wqs[i] = wqs[i]; s_wks[i] = wks[i];
    }
    for (int i = threadIdx.x; i < 1024; i += 128) { s_wv[i] = wv[i]; s_wvs[i] = wvs[i]; }
    if (threadIdx.x < 16) {
        s_bq[threadIdx.x] = bq[threadIdx.x]; s_bk[threadIdx.x] = bk[threadIdx.x];
        s_bqs[threadIdx.x] = bqs[threadIdx.x]; s_bks[threadIdx.x] = bks[threadIdx.x];
    }
    if (threadIdx.x < 32) { s_bv[threadIdx.x] = bv[threadIdx.x]; s_bvs[threadIdx.x] = bvs[threadIdx.x]; }
    __syncthreads();

    int idx = blockIdx.x * 128 + threadIdx.x;          // < NB*NP
    int b = idx / NP, p = idx % NP, t = p / (HHd * WWd);

    float xd[32], xcd[32];
#pragma unroll
    for (int c = 0; c < 32; c++) {
        xd[c]  = g_xd [(b * 32 + c) * NP + p];
        xcd[c] = g_xcd[(b * 32 + c) * NP + p];
    }

    const float invf[8] = {1.0f, 0.31622776601683794f, 0.1f, 0.031622776601683794f,
                           0.01f, 0.0031622776601683794f, 0.001f, 0.00031622776601683794f};
    float se[8], ce[8], sc[8], cc[8];
    float tf = (float)t;
#pragma unroll
    for (int i = 0; i < 8; i++) {
        float a = tf * invf[i];
        float s = sinf(a), c = cosf(a);
        float o1 = off[i * 500 + t];
        float o2 = offc[i * 500 + t];
        se[i] = s + o1; ce[i] = c + o1;     // same offset added to sin AND cos (per reference)
        sc[i] = s + o2; cc[i] = c + o2;
    }

    float tmp[16];
#pragma unroll
    for (int o = 0; o < 16; o++) {
        float acc = s_bq[o];
#pragma unroll
        for (int c = 0; c < 32; c++) acc = fmaf(s_wq[o * 32 + c], xd[c], acc);
        tmp[o] = acc;
    }
#pragma unroll
    for (int i = 0; i < 8; i++) {
        g_q[(b * 16 + i)     * NP + p] = 0.5f * (tmp[i] * ce[i] - tmp[8 + i] * se[i]);
        g_q[(b * 16 + 8 + i) * NP + p] = 0.5f * (tmp[8 + i] * ce[i] + tmp[i] * se[i]);
    }
#pragma unroll
    for (int o = 0; o < 16; o++) {
        float acc = s_bk[o];
#pragma unroll
        for (int c = 0; c < 32; c++) acc = fmaf(s_wk[o * 32 + c], xcd[c], acc);
        tmp[o] = acc;
    }
#pragma unroll
    for (int i = 0; i < 8; i++) {
        g_k[(b * 16 + i)     * NP + p] = tmp[i] * cc[i] - tmp[8 + i] * sc[i];
        g_k[(b * 16 + 8 + i) * NP + p] = tmp[8 + i] * cc[i] + tmp[i] * sc[i];
    }
#pragma unroll
    for (int o = 0; o < 32; o++) {
        float acc = s_bv[o];
#pragma unroll
        for (int c = 0; c < 32; c++) acc = fmaf(s_wv[o * 32 + c], xcd[c], acc);
        g_v[(b * 32 + o) * NP + p] = acc;
    }
#pragma unroll
    for (int o = 0; o < 16; o++) {
        float acc = s_bqs[o];
#pragma unroll
        for (int c = 0; c < 32; c++) acc = fmaf(s_wqs[o * 32 + c], xcd[c], acc);
        tmp[o] = acc;
    }
#pragma unroll
    for (int i = 0; i < 8; i++) {
        g_qsa[(b * 16 + i)     * NP + p] = 0.5f * (tmp[i] * ce[i] - tmp[8 + i] * se[i]);
        g_qsa[(b * 16 + 8 + i) * NP + p] = 0.5f * (tmp[8 + i] * ce[i] + tmp[i] * se[i]);
    }
#pragma unroll
    for (int o = 0; o < 16; o++) {
        float acc = s_bks[o];
#pragma unroll
        for (int c = 0; c < 32; c++) acc = fmaf(s_wks[o * 32 + c], xcd[c], acc);
        tmp[o] = acc;
    }
#pragma unroll
    for (int i = 0; i < 8; i++) {
        g_ksa[(b * 16 + i)     * NP + p] = tmp[i] * ce[i] - tmp[8 + i] * se[i];
        g_ksa[(b * 16 + 8 + i) * NP + p] = tmp[8 + i] * ce[i] + tmp[i] * se[i];
    }
#pragma unroll
    for (int o = 0; o < 32; o++) {
        float acc = s_bvs[o];
#pragma unroll
        for (int c = 0; c < 32; c++) acc = fmaf(s_wvs[o * 32 + c], xcd[c], acc);
        g_vsa[(b * 32 + o) * NP + p] = acc;
    }
}

// ---------------- K4: split-K flash attention, key batching of 8 ----------------
__global__ __launch_bounds__(128) void k_attn(){
    int a  = blockIdx.z / SPLIT;      // 0 = cross, 1 = self
    int sp = blockIdx.z % SPLIT;
    int b  = blockIdx.y;
    const float *Q, *K, *V;
    if (a == 0) { Q = g_q;   K = g_k;   V = g_v;   }
    else        { Q = g_qsa; K = g_ksa; V = g_vsa; }
    Q += b * 16 * NP; K += b * 16 * NP; V += b * 32 * NP;

    __shared__ __align__(16) float sK[128][20];
    __shared__ __align__(16) float sV[128][36];

    int tid = threadIdx.x;
    int qi = blockIdx.x * 128 + tid;

    u64 q2[8];
#pragma unroll
    for (int i = 0; i < 8; i++) q2[i] = pk2(Q[(2 * i) * NP + qi], Q[(2 * i + 1) * NP + qi]);

    u64 acc[16];
#pragma unroll
    for (int i = 0; i < 16; i++) acc[i] = pk2(0.0f, 0.0f);
    float m = -1e30f, l = 0.0f;

    for (int j0 = sp * KCH; j0 < (sp + 1) * KCH; j0 += 128) {
        __syncthreads();
#pragma unroll
        for (int c = 0; c < 16; c++) sK[tid][c] = K[c * NP + j0 + tid];
#pragma unroll
        for (int c = 0; c < 32; c++) sV[tid][c] = V[c * NP + j0 + tid];
        __syncthreads();
#pragma unroll 2
        for (int jb = 0; jb < 128; jb += 8) {
            float s[8];
#pragma unroll
            for (int jj = 0; jj < 8; jj++) {
                const u64* kr = (const u64*)sK[jb + jj];
                u64 sa = fmul2(q2[0], kr[0]);
                u64 sb = fmul2(q2[1], kr[1]);
                sa = ffma2(q2[2], kr[2], sa);
                sb = ffma2(q2[3], kr[3], sb);
                sa = ffma2(q2[4], kr[4], sa);
                sb = ffma2(q2[5], kr[5], sb);
                sa = ffma2(q2[6], kr[6], sa);
                sb = ffma2(q2[7], kr[7], sb);
                sa = fadd2(sa, sb);
                float s0, s1; up2(sa, s0, s1);
                s[jj] = s0 + s1;
            }
            float bm0 = fmaxf(s[0], s[1]), bm1 = fmaxf(s[2], s[3]);
            float bm2 = fmaxf(s[4], s[5]), bm3 = fmaxf(s[6], s[7]);
            float bmax = fmaxf(fmaxf(bm0, bm1), fmaxf(bm2, bm3));
            if (bmax > m) {
                float corr = __expf(m - bmax);
                m = bmax;
                l *= corr;
                u64 c2 = pk2(corr, corr);
#pragma unroll
                for (int i = 0; i < 16; i++) acc[i] = fmul2(acc[i], c2);
            }
            float p[8];
#pragma unroll
            for (int jj = 0; jj < 8; jj++) p[jj] = __expf(s[jj] - m);
            l += ((p[0] + p[1]) + (p[2] + p[3])) + ((p[4] + p[5]) + (p[6] + p[7]));
#pragma unroll
            for (int jj = 0; jj < 8; jj++) {
                u64 p2 = pk2(p[jj], p[jj]);
                const u64* vr = (const u64*)sV[jb + jj];
#pragma unroll
                for (int i = 0; i < 16; i++) acc[i] = ffma2(p2, vr[i], acc[i]);
            }
        }
    }
    // write partials
    float* pa = g_pacc + (size_t)(((a * NB + b) * SPLIT + sp) * 32) * NP;
    float* pm = g_pml  + (size_t)(((a * NB + b) * SPLIT + sp) * 2) * NP;
#pragma unroll
    for (int i = 0; i < 16; i++) {
        float a0, a1; up2(acc[i], a0, a1);
        pa[(2 * i)     * NP + qi] = a0;
        pa[(2 * i + 1) * NP + qi] = a1;
    }
    pm[qi]      = m;
    pm[NP + qi] = l;
}

// ---------------- K4b: split-K reduce ----------------
__global__ __launch_bounds__(128) void k_attn_red() {
    int a = blockIdx.z, b = blockIdx.y;
    int qi = blockIdx.x * 128 + threadIdx.x;
    const float* pm_base = g_pml  + (size_t)((a * NB + b) * SPLIT) * 2 * NP;
    const float* pa_base = g_pacc + (size_t)((a * NB + b) * SPLIT) * 32 * NP;

    float m = -1e30f;
    float ms[SPLIT];
#pragma unroll
    for (int sp = 0; sp < SPLIT; sp++) {
        ms[sp] = pm_base[sp * 2 * NP + qi];
        m = fmaxf(m, ms[sp]);
    }
    float w[SPLIT]; float l = 0.0f;
#pragma unroll
    for (int sp = 0; sp < SPLIT; sp++) {
        w[sp] = __expf(ms[sp] - m);
        l += pm_base[(sp * 2 + 1) * NP + qi] * w[sp];
    }
    float inv = 1.0f / l;
    float* O = g_ao[a] + b * 32 * NP;
#pragma unroll
    for (int c = 0; c < 32; c++) {
        float s = 0.0f;
#pragma unroll
        for (int sp = 0; sp < SPLIT; sp++)
            s = fmaf(pa_base[(sp * 32 + c) * NP + qi], w[sp], s);
        O[c * NP + qi] = s * inv;
    }
}

// ---------------- K5: groupnorm partial stats (deterministic, no atomics) ----------------
__global__ __launch_bounds__(256) void k_stats() {
    int gb = blockIdx.x >> 3;            // attn*2 + b
    int ch = blockIdx.x & 7;             // chunk
    int aa = gb >> 1, b = gb & 1;
    const float* src = g_ao[aa] + b * 32 * NP + ch * (NTOT / 8);
    float s1 = 0.0f;
    double s2 = 0.0;
    for (int i = threadIdx.x; i < NTOT / 8; i += 256) {
        float v = src[i];
        s1 += v;
        s2 += (double)v * (double)v;
    }
    __shared__ float  r1[256];
    __shared__ double r2[256];
    r1[threadIdx.x] = s1; r2[threadIdx.x] = s2;
    __syncthreads();
    for (int s = 128; s > 0; s >>= 1) {
        if (threadIdx.x < s) { r1[threadIdx.x] += r1[threadIdx.x + s]; r2[threadIdx.x] += r2[threadIdx.x + s]; }
        __syncthreads();
    }
    if (threadIdx.x == 0) {
        g_psum[gb][ch][0] = (double)r1[0];
        g_psum[gb][ch][1] = r2[0];
    }
}

// ---------------- K6: groupnorm apply + up conv 32 -> 64 ----------------
__global__ __launch_bounds__(128) void k_gnup(
    const float* __restrict__ gnw,  const float* __restrict__ gnb,
    const float* __restrict__ gnws, const float* __restrict__ gnbs,
    const float* __restrict__ wup,  const float* __restrict__ bup,
    const float* __restrict__ wups, const float* __restrict__ bups) {
    int a = blockIdx.z, b = blockIdx.y;
    int gb = a * 2 + b;
    __shared__ float sw[64 * 32];
    __shared__ float sb2[64], sa_[32], sd_[32];
    const float* w   = a ? wups : wup;
    const float* bb  = a ? bups : bup;
    const float* gw  = a ? gnws : gnw;
    const float* gbb = a ? gnbs : gnb;
    double s1 = 0.0, s2 = 0.0;
#pragma unroll
    for (int c = 0; c < 8; c++) { s1 += g_psum[gb][c][0]; s2 += g_psum[gb][c][1]; }
    double mu_d  = s1 / (double)NTOT;
    double var_d = s2 / (double)NTOT - mu_d * mu_d;
    float mu = (float)mu_d;
    float rstd = rsqrtf((float)var_d + 1e-5f);
    for (int i = threadIdx.x; i < 2048; i += 128) sw[i] = w[i];
    if (threadIdx.x < 64) sb2[threadIdx.x] = bb[threadIdx.x];
    if (threadIdx.x < 32) {
        float aa = rstd * gw[threadIdx.x];
        sa_[threadIdx.x] = aa;
        sd_[threadIdx.x] = gbb[threadIdx.x] - mu * aa;
    }
    __syncthreads();
    int p = blockIdx.x * 128 + threadIdx.x;
    const float* src = g_ao[a] + b * 32 * NP;
    float xn[32];
#pragma unroll
    for (int c = 0; c < 32; c++) xn[c] = fmaf(src[c * NP + p], sa_[c], sd_[c]);
    float* dst = g_up[a] + b * 64 * NP;
#pragma unroll
    for (int o = 0; o < 64; o++) {
        float acc = sb2[o];
#pragma unroll
        for (int c = 0; c < 32; c++) acc = fmaf(sw[o * 32 + c], xn[c], acc);
        dst[o * NP + p] = acc;
    }
}

// ---------------- K7: upsample both branches + combine ----------------
__device__ __forceinline__ float tri8(const float* __restrict__ s,
                                      int p00, int p01, int p10, int p11,
                                      int w0, int w1, float ww, float wh, float wt) {
    float c00 = s[p00 + w0]; c00 += (s[p00 + w1] - c00) * ww;
    float c01 = s[p01 + w0]; c01 += (s[p01 + w1] - c01) * ww;
    float c10 = s[p10 + w0]; c10 += (s[p10 + w1] - c10) * ww;
    float c11 = s[p11 + w0]; c11 += (s[p11 + w1] - c11) * ww;
    float c0 = c00 + (c01 - c00) * wh;
    float c1 = c10 + (c11 - c10) * wh;
    return c0 + (c1 - c0) * wt;
}

__global__ void k_final(const float* __restrict__ xc, float* __restrict__ out) {
    int idx = blockIdx.x * 256 + threadIdx.x;          // < 2*64*16*48*48
    int w = idx % WF;
    int h = (idx / WF) % HF;
    int t = (idx / (WF * HF)) % TF;
    int bc = idx / (WF * HF * TF);                     // b*64 + c

    float pt = (float)t * (7.0f / 15.0f);
    int t0 = (int)pt; float wt = pt - (float)t0; int t1 = min(t0 + 1, 7); t0 = min(t0, 7);
    float ph = (float)h * (23.0f / 47.0f);
    int h0 = (int)ph; float wh = ph - (float)h0; int h1 = min(h0 + 1, 23); h0 = min(h0, 23);
    float pw = (float)w * (23.0f / 47.0f);
    int w0 = (int)pw; float ww = pw - (float)w0; int w1 = min(w0 + 1, 23); w0 = min(w0, 23);

    int base = bc * NP;
    int p00 = t0 * (HHd * WWd) + h0 * WWd;
    int p01 = t0 * (HHd * WWd) + h1 * WWd;
    int p10 = t1 * (HHd * WWd) + h0 * WWd;
    int p11 = t1 * (HHd * WWd) + h1 * WWd;

    float r_cross = tri8(g_up[0] + base, p00, p01, p10, p11, w0, w1, ww, wh, wt);
    float r_self  = tri8(g_up[1] + base, p00, p01, p10, p11, w0, w1, ww, wh, wt);
    out[idx] = r_self + xc[idx] - 0.5f * r_cross;
}

// ---------------- launch ----------------
extern "C" void kernel_launch(void* const* d_in, const int* in_sizes, int n_in,
                              void* d_out, int out_size) {
    const float* x       = (const float*)d_in[0];
    const float* x_c     = (const float*)d_in[1];
    const float* w_down  = (const float*)d_in[2];
    const float* b_down  = (const float*)d_in[3];
    const float* w_downc = (const float*)d_in[4];
    const float* b_downc = (const float*)d_in[5];
    const float* w_q     = (const float*)d_in[6];
    const float* b_q     = (const float*)d_in[7];
    const float* w_k     = (const float*)d_in[8];
    const float* b_k     = (const float*)d_in[9];
    const float* w_v     = (const float*)d_in[10];
    const float* b_v     = (const float*)d_in[11];
    const float* w_qsa   = (const float*)d_in[12];
    const float* b_qsa   = (const float*)d_in[13];
    const float* w_ksa   = (const float*)d_in[14];
    const float* b_ksa   = (const float*)d_in[15];
    const float* w_vsa   = (const float*)d_in[16];
    const float* b_vsa   = (const float*)d_in[17];
    const float* gn_w    = (const float*)d_in[18];
    const float* gn_b    = (const float*)d_in[19];
    const float* gn_wsa  = (const float*)d_in[20];
    const float* gn_bsa  = (const float*)d_in[21];
    const float* w_up    = (const float*)d_in[22];
    const float* b_up    = (const float*)d_in[23];
    const float* w_upsa  = (const float*)d_in[24];
    const float* b_upsa  = (const float*)d_in[25];
    const float* offset  = (const float*)d_in[26];
    const float* offsetc = (const float*)d_in[27];

    dim3 g1(2304, 1, 2);
    k_resize<<<g1, 256>>>(x, x_c);

    dim3 g2(72, 1, 2);
    k_down<<<g2, 128>>>(w_down, b_down, w_downc, b_downc);

    k_proj<<<72, 128>>>(w_q, b_q, w_k, b_k, w_v, b_v,
                        w_qsa, b_qsa, w_ksa, b_ksa, w_vsa, b_vsa,
                        offset, offsetc);

    dim3 g4(36, NB, 2 * SPLIT);
    k_attn<<<g4, 128>>>();

    dim3 g4b(36, NB, 2);
    k_attn_red<<<g4b, 128>>>();

    k_stats<<<32, 256>>>();

    dim3 g6(36, NB, 2);
    k_gnup<<<g6, 128>>>(gn_w, gn_b, gn_wsa, gn_bsa, w_up, b_up, w_upsa, b_upsa);

    k_final<<<18432, 256>>>(x_c, (float*)d_out);
}

// round 5
// speedup vs baseline: 1.7668x; 1.0383x over previous
#include <cuda_runtime.h>
#include <math_constants.h>

// ---------------- constants ----------------
#define NB    2
#define CIN   64
#define CD    32
#define TT    8
#define HHd   24
#define WWd   24
#define NP    4608          // TT*HHd*WWd
#define TF    16
#define HF    48
#define WF    48
#define NTOT  (32*NP)       // groupnorm element count per (attn,b)
#define SPLIT 6
#define KCH   (NP/SPLIT)    // 768 keys per split

// ---------------- scratch (device globals; no allocation) ----------------
__device__ float g_xr [NB*CIN*NP];
__device__ float g_xcr[NB*CIN*NP];
__device__ float g_xd [NB*CD*NP];
__device__ float g_xcd[NB*CD*NP];
__device__ float g_q  [NB*16*NP];
__device__ float g_k  [NB*16*NP];
__device__ float g_v  [NB*32*NP];
__device__ float g_qsa[NB*16*NP];
__device__ float g_ksa[NB*16*NP];
__device__ float g_vsa[NB*32*NP];
__device__ float g_pacc[2*NB*SPLIT*32*NP];   // split-K partial acc
__device__ float g_pml [2*NB*SPLIT*2*NP];    // split-K partial m,l
__device__ float g_ao [2][NB*32*NP];         // attention outputs (cross, self)
__device__ float g_up [2][NB*64*NP];         // after GN + up conv, before upsample
__device__ double g_psum[4][8][2];           // GN partial sums [gb][chunk][s1,s2]

// ---------------- f32x2 packed helpers ----------------
typedef unsigned long long u64;
__device__ __forceinline__ u64 pk2(float lo, float hi) {
    u64 r; asm("mov.b64 %0, {%1, %2};" : "=l"(r) : "f"(lo), "f"(hi)); return r;
}
__device__ __forceinline__ void up2(u64 v, float& lo, float& hi) {
    asm("mov.b64 {%0, %1}, %2;" : "=f"(lo), "=f"(hi) : "l"(v));
}
__device__ __forceinline__ u64 ffma2(u64 a, u64 b, u64 c) {
    u64 d; asm("fma.rn.f32x2 %0, %1, %2, %3;" : "=l"(d) : "l"(a), "l"(b), "l"(c)); return d;
}
__device__ __forceinline__ u64 fmul2(u64 a, u64 b) {
    u64 d; asm("mul.rn.f32x2 %0, %1, %2;" : "=l"(d) : "l"(a), "l"(b)); return d;
}
__device__ __forceinline__ u64 fadd2(u64 a, u64 b) {
    u64 d; asm("add.rn.f32x2 %0, %1, %2;" : "=l"(d) : "l"(a), "l"(b)); return d;
}

// ---------------- K1: trilinear downsample (16,48,48)->(8,24,24) ----------------
__global__ void k_resize(const float* __restrict__ x, const float* __restrict__ xc) {
    int i = blockIdx.x * 256 + threadIdx.x;            // < NB*CIN*NP
    const float* src = blockIdx.z ? xc : x;
    float* dst = blockIdx.z ? g_xcr : g_xr;
    int p  = i % NP;
    int bc = i / NP;
    int w = p % WWd, h = (p / WWd) % HHd, t = p / (WWd * HHd);

    float pt = (float)t * (15.0f / 7.0f);
    int t0 = (int)pt; float wt = pt - (float)t0; int t1 = min(t0 + 1, 15); t0 = min(t0, 15);
    float ph = (float)h * (47.0f / 23.0f);
    int h0 = (int)ph; float wh = ph - (float)h0; int h1 = min(h0 + 1, 47); h0 = min(h0, 47);
    float pw = (float)w * (47.0f / 23.0f);
    int w0 = (int)pw; float ww = pw - (float)w0; int w1 = min(w0 + 1, 47); w0 = min(w0, 47);

    const float* base = src + (size_t)bc * (TF * HF * WF);
#define ATI(ti,hi,wi) __ldg(base + (ti)*(HF*WF) + (hi)*WF + (wi))
    float c00 = ATI(t0,h0,w0); c00 += (ATI(t0,h0,w1) - c00) * ww;
    float c01 = ATI(t0,h1,w0); c01 += (ATI(t0,h1,w1) - c01) * ww;
    float c10 = ATI(t1,h0,w0); c10 += (ATI(t1,h0,w1) - c10) * ww;
    float c11 = ATI(t1,h1,w0); c11 += (ATI(t1,h1,w1) - c11) * ww;
#undef ATI
    float c0 = c00 + (c01 - c00) * wh;
    float c1 = c10 + (c11 - c10) * wh;
    dst[i] = c0 + (c1 - c0) * wt;
}

// ---------------- K2: down conv 64 -> 32 ----------------
__global__ __launch_bounds__(128) void k_down(
    const float* __restrict__ wd, const float* __restrict__ bd,
    const float* __restrict__ wdc, const float* __restrict__ bdc) {
    __shared__ float sw[CD * CIN];
    __shared__ float sb[CD];
    const float* w  = blockIdx.z ? wdc : wd;
    const float* bb = blockIdx.z ? bdc : bd;
    const float* in = blockIdx.z ? g_xcr : g_xr;
    float* out      = blockIdx.z ? g_xcd : g_xd;
    for (int i = threadIdx.x; i < CD * CIN; i += 128) sw[i] = w[i];
    if (threadIdx.x < CD) sb[threadIdx.x] = bb[threadIdx.x];
    __syncthreads();
    int idx = blockIdx.x * 128 + threadIdx.x;          // < NB*NP
    int b = idx / NP, p = idx % NP;
    float xin[CIN];
#pragma unroll
    for (int c = 0; c < CIN; c++) xin[c] = in[(b * CIN + c) * NP + p];
#pragma unroll
    for (int o = 0; o < CD; o++) {
        float acc = sb[o];
#pragma unroll
        for (int c = 0; c < CIN; c++) acc = fmaf(sw[o * CIN + c], xin[c], acc);
        out[(b * CD + o) * NP + p] = acc;
    }
}

// ---------------- K3: QKV projections + RoPE (scale folded into q) ----------------
__global__ __launch_bounds__(128) void k_proj(
    const float* __restrict__ wq,  const float* __restrict__ bq,
    const float* __restrict__ wk,  const float* __restrict__ bk,
    const float* __restrict__ wv,  const float* __restrict__ bv,
    const float* __restrict__ wqs, const float* __restrict__ bqs,
    const float* __restrict__ wks, const float* __restrict__ bks,
    const float* __restrict__ wvs, const float* __restrict__ bvs,
    const float* __restrict__ off, const float* __restrict__ offc) {
    __shared__ float s_wq[512], s_wk[512], s_wqs[512], s_wks[512];
    __shared__ float s_wv[1024], s_wvs[1024];
    __shared__ float s_bq[16], s_bk[16], s_bqs[16], s_bks[16], s_bv[32], s_bvs[32];
    for (int i = threadIdx.x; i < 512; i += 128) {
        s_wq[i] = wq[i]; s_wk[i] = wk[i]; s_wqs[i] = wqs[i]; s_wks[i] = wks[i];
    }
    for (int i = threadIdx.x; i < 1024; i += 128) { s_wv[i] = wv[i]; s_wvs[i] = wvs[i]; }
    if (threadIdx.x < 16) {
        s_bq[threadIdx.x] = bq[threadIdx.x]; s_bk[threadIdx.x] = bk[threadIdx.x];
        s_bqs[threadIdx.x] = bqs[threadIdx.x]; s_bks[threadIdx.x] = bks[threadIdx.x];
    }
    if (threadIdx.x < 32) { s_bv[threadIdx.x] = bv[threadIdx.x]; s_bvs[threadIdx.x] = bvs[threadIdx.x]; }
    __syncthreads();

    int idx = blockIdx.x * 128 + threadIdx.x;          // < NB*NP
    int b = idx / NP, p = idx % NP, t = p / (HHd * WWd);

    float xd[32], xcd[32];
#pragma unroll
    for (int c = 0; c < 32; c++) {
        xd[c]  = g_xd [(b * 32 + c) * NP + p];
        xcd[c] = g_xcd[(b * 32 + c) * NP + p];
    }

    const float invf[8] = {1.0f, 0.31622776601683794f, 0.1f, 0.031622776601683794f,
                           0.01f, 0.0031622776601683794f, 0.001f, 0.00031622776601683794f};
    float se[8], ce[8], sc[8], cc[8];
    float tf = (float)t;
#pragma unroll
    for (int i = 0; i < 8; i++) {
        float a = tf * invf[i];
        float s = sinf(a), c = cosf(a);
        float o1 = off[i * 500 + t];
        float o2 = offc[i * 500 + t];
        se[i] = s + o1; ce[i] = c + o1;     // same offset added to sin AND cos (per reference)
        sc[i] = s + o2; cc[i] = c + o2;
    }

    float tmp[16];
#pragma unroll
    for (int o = 0; o < 16; o++) {
        float acc = s_bq[o];
#pragma unroll
        for (int c = 0; c < 32; c++) acc = fmaf(s_wq[o * 32 + c], xd[c], acc);
        tmp[o] = acc;
    }
#pragma unroll
    for (int i = 0; i < 8; i++) {
        g_q[(b * 16 + i)     * NP + p] = 0.5f * (tmp[i] * ce[i] - tmp[8 + i] * se[i]);
        g_q[(b * 16 + 8 + i) * NP + p] = 0.5f * (tmp[8 + i] * ce[i] + tmp[i] * se[i]);
    }
#pragma unroll
    for (int o = 0; o < 16; o++) {
        float acc = s_bk[o];
#pragma unroll
        for (int c = 0; c < 32; c++) acc = fmaf(s_wk[o * 32 + c], xcd[c], acc);
        tmp[o] = acc;
    }
#pragma unroll
    for (int i = 0; i < 8; i++) {
        g_k[(b * 16 + i)     * NP + p] = tmp[i] * cc[i] - tmp[8 + i] * sc[i];
        g_k[(b * 16 + 8 + i) * NP + p] = tmp[8 + i] * cc[i] + tmp[i] * sc[i];
    }
#pragma unroll
    for (int o = 0; o < 32; o++) {
        float acc = s_bv[o];
#pragma unroll
        for (int c = 0; c < 32; c++) acc = fmaf(s_wv[o * 32 + c], xcd[c], acc);
        g_v[(b * 32 + o) * NP + p] = acc;
    }
#pragma unroll
    for (int o = 0; o < 16; o++) {
        float acc = s_bqs[o];
#pragma unroll
        for (int c = 0; c < 32; c++) acc = fmaf(s_wqs[o * 32 + c], xcd[c], acc);
        tmp[o] = acc;
    }
#pragma unroll
    for (int i = 0; i < 8; i++) {
        g_qsa[(b * 16 + i)     * NP + p] = 0.5f * (tmp[i] * ce[i] - tmp[8 + i] * se[i]);
        g_qsa[(b * 16 + 8 + i) * NP + p] = 0.5f * (tmp[8 + i] * ce[i] + tmp[i] * se[i]);
    }
#pragma unroll
    for (int o = 0; o < 16; o++) {
        float acc = s_bks[o];
#pragma unroll
        for (int c = 0; c < 32; c++) acc = fmaf(s_wks[o * 32 + c], xcd[c], acc);
        tmp[o] = acc;
    }
#pragma unroll
    for (int i = 0; i < 8; i++) {
        g_ksa[(b * 16 + i)     * NP + p] = tmp[i] * ce[i] - tmp[8 + i] * se[i];
        g_ksa[(b * 16 + 8 + i) * NP + p] = tmp[8 + i] * ce[i] + tmp[i] * se[i];
    }
#pragma unroll
    for (int o = 0; o < 32; o++) {
        float acc = s_bvs[o];
#pragma unroll
        for (int c = 0; c < 32; c++) acc = fmaf(s_wvs[o * 32 + c], xcd[c], acc);
        g_vsa[(b * 32 + o) * NP + p] = acc;
    }
}

// ---------------- K4: split-K flash attention, 2 queries/thread, LDS.128 ----------------
__global__ __launch_bounds__(128) void k_attn(){
    int a  = blockIdx.z / SPLIT;      // 0 = cross, 1 = self
    int sp = blockIdx.z % SPLIT;
    int b  = blockIdx.y;
    const float *Q, *K, *V;
    if (a == 0) { Q = g_q;   K = g_k;   V = g_v;   }
    else        { Q = g_qsa; K = g_ksa; V = g_vsa; }
    Q += b * 16 * NP; K += b * 16 * NP; V += b * 32 * NP;

    __shared__ __align__(16) float sK[128][20];
    __shared__ __align__(16) float sV[128][36];

    int tid = threadIdx.x;
    int qa_i = blockIdx.x * 256 + tid;       // query A
    int qb_i = qa_i + 128;                   // query B

    u64 qa[8], qb[8];
#pragma unroll
    for (int i = 0; i < 8; i++) {
        qa[i] = pk2(Q[(2 * i) * NP + qa_i], Q[(2 * i + 1) * NP + qa_i]);
        qb[i] = pk2(Q[(2 * i) * NP + qb_i], Q[(2 * i + 1) * NP + qb_i]);
    }

    u64 acca[16], accb[16];
#pragma unroll
    for (int i = 0; i < 16; i++) { acca[i] = pk2(0.0f, 0.0f); accb[i] = pk2(0.0f, 0.0f); }
    float ma = -1e30f, la = 0.0f;
    float mb = -1e30f, lb = 0.0f;

    for (int j0 = sp * KCH; j0 < (sp + 1) * KCH; j0 += 128) {
        __syncthreads();
#pragma unroll
        for (int c = 0; c < 16; c++) sK[tid][c] = K[c * NP + j0 + tid];
#pragma unroll
        for (int c = 0; c < 32; c++) sV[tid][c] = V[c * NP + j0 + tid];
        __syncthreads();
#pragma unroll 2
        for (int jb = 0; jb < 128; jb += 4) {
            float sa[4], sb[4];
#pragma unroll
            for (int jj = 0; jj < 4; jj++) {
                const ulonglong2* kr = (const ulonglong2*)sK[jb + jj];
                ulonglong2 k0 = kr[0], k1 = kr[1], k2 = kr[2], k3 = kr[3];
                u64 ta0 = fmul2(qa[0], k0.x);
                u64 ta1 = fmul2(qa[1], k0.y);
                u64 tb0 = fmul2(qb[0], k0.x);
                u64 tb1 = fmul2(qb[1], k0.y);
                ta0 = ffma2(qa[2], k1.x, ta0);
                ta1 = ffma2(qa[3], k1.y, ta1);
                tb0 = ffma2(qb[2], k1.x, tb0);
                tb1 = ffma2(qb[3], k1.y, tb1);
                ta0 = ffma2(qa[4], k2.x, ta0);
                ta1 = ffma2(qa[5], k2.y, ta1);
                tb0 = ffma2(qb[4], k2.x, tb0);
                tb1 = ffma2(qb[5], k2.y, tb1);
                ta0 = ffma2(qa[6], k3.x, ta0);
                ta1 = ffma2(qa[7], k3.y, ta1);
                tb0 = ffma2(qb[6], k3.x, tb0);
                tb1 = ffma2(qb[7], k3.y, tb1);
                ta0 = fadd2(ta0, ta1);
                tb0 = fadd2(tb0, tb1);
                float a0, a1, b0, b1;
                up2(ta0, a0, a1); sa[jj] = a0 + a1;
                up2(tb0, b0, b1); sb[jj] = b0 + b1;
            }
            float bma = fmaxf(fmaxf(sa[0], sa[1]), fmaxf(sa[2], sa[3]));
            float bmb = fmaxf(fmaxf(sb[0], sb[1]), fmaxf(sb[2], sb[3]));
            if (bma > ma) {
                float corr = __expf(ma - bma);
                ma = bma; la *= corr;
                u64 c2 = pk2(corr, corr);
#pragma unroll
                for (int i = 0; i < 16; i++) acca[i] = fmul2(acca[i], c2);
            }
            if (bmb > mb) {
                float corr = __expf(mb - bmb);
                mb = bmb; lb *= corr;
                u64 c2 = pk2(corr, corr);
#pragma unroll
                for (int i = 0; i < 16; i++) accb[i] = fmul2(accb[i], c2);
            }
            float pa[4], pb[4];
#pragma unroll
            for (int jj = 0; jj < 4; jj++) {
                pa[jj] = __expf(sa[jj] - ma);
                pb[jj] = __expf(sb[jj] - mb);
            }
            la += (pa[0] + pa[1]) + (pa[2] + pa[3]);
            lb += (pb[0] + pb[1]) + (pb[2] + pb[3]);
#pragma unroll
            for (int jj = 0; jj < 4; jj++) {
                const ulonglong2* vr = (const ulonglong2*)sV[jb + jj];
                u64 p2a = pk2(pa[jj], pa[jj]);
                u64 p2b = pk2(pb[jj], pb[jj]);
#pragma unroll
                for (int i = 0; i < 8; i++) {
                    ulonglong2 v = vr[i];
                    acca[2 * i]     = ffma2(p2a, v.x, acca[2 * i]);
                    acca[2 * i + 1] = ffma2(p2a, v.y, acca[2 * i + 1]);
                    accb[2 * i]     = ffma2(p2b, v.x, accb[2 * i]);
                    accb[2 * i + 1] = ffma2(p2b, v.y, accb[2 * i + 1]);
                }
            }
        }
    }
    // write partials
    float* pa_ = g_pacc + (size_t)(((a * NB + b) * SPLIT + sp) * 32) * NP;
    float* pm_ = g_pml  + (size_t)(((a * NB + b) * SPLIT + sp) * 2) * NP;
#pragma unroll
    for (int i = 0; i < 16; i++) {
        float a0, a1;
        up2(acca[i], a0, a1);
        pa_[(2 * i)     * NP + qa_i] = a0;
        pa_[(2 * i + 1) * NP + qa_i] = a1;
        up2(accb[i], a0, a1);
        pa_[(2 * i)     * NP + qb_i] = a0;
        pa_[(2 * i + 1) * NP + qb_i] = a1;
    }
    pm_[qa_i]      = ma;
    pm_[NP + qa_i] = la;
    pm_[qb_i]      = mb;
    pm_[NP + qb_i] = lb;
}

// ---------------- K4b: split-K reduce ----------------
__global__ __launch_bounds__(128) void k_attn_red() {
    int a = blockIdx.z, b = blockIdx.y;
    int qi = blockIdx.x * 128 + threadIdx.x;
    const float* pm_base = g_pml  + (size_t)((a * NB + b) * SPLIT) * 2 * NP;
    const float* pa_base = g_pacc + (size_t)((a * NB + b) * SPLIT) * 32 * NP;

    float m = -1e30f;
    float ms[SPLIT];
#pragma unroll
    for (int sp = 0; sp < SPLIT; sp++) {
        ms[sp] = pm_base[sp * 2 * NP + qi];
        m = fmaxf(m, ms[sp]);
    }
    float w[SPLIT]; float l = 0.0f;
#pragma unroll
    for (int sp = 0; sp < SPLIT; sp++) {
        w[sp] = __expf(ms[sp] - m);
        l += pm_base[(sp * 2 + 1) * NP + qi] * w[sp];
    }
    float inv = 1.0f / l;
    float* O = g_ao[a] + b * 32 * NP;
#pragma unroll
    for (int c = 0; c < 32; c++) {
        float s = 0.0f;
#pragma unroll
        for (int sp = 0; sp < SPLIT; sp++)
            s = fmaf(pa_base[(sp * 32 + c) * NP + qi], w[sp], s);
        O[c * NP + qi] = s * inv;
    }
}

// ---------------- K5: groupnorm partial stats (deterministic, no atomics) ----------------
__global__ __launch_bounds__(256) void k_stats() {
    int gb = blockIdx.x >> 3;            // attn*2 + b
    int ch = blockIdx.x & 7;             // chunk
    int aa = gb >> 1, b = gb & 1;
    const float* src = g_ao[aa] + b * 32 * NP + ch * (NTOT / 8);
    float s1 = 0.0f;
    double s2 = 0.0;
    for (int i = threadIdx.x; i < NTOT / 8; i += 256) {
        float v = src[i];
        s1 += v;
        s2 += (double)v * (double)v;
    }
    __shared__ float  r1[256];
    __shared__ double r2[256];
    r1[threadIdx.x] = s1; r2[threadIdx.x] = s2;
    __syncthreads();
    for (int s = 128; s > 0; s >>= 1) {
        if (threadIdx.x < s) { r1[threadIdx.x] += r1[threadIdx.x + s]; r2[threadIdx.x] += r2[threadIdx.x + s]; }
        __syncthreads();
    }
    if (threadIdx.x == 0) {
        g_psum[gb][ch][0] = (double)r1[0];
        g_psum[gb][ch][1] = r2[0];
    }
}

// ---------------- K6: groupnorm apply + up conv 32 -> 64 ----------------
__global__ __launch_bounds__(128) void k_gnup(
    const float* __restrict__ gnw,  const float* __restrict__ gnb,
    const float* __restrict__ gnws, const float* __restrict__ gnbs,
    const float* __restrict__ wup,  const float* __restrict__ bup,
    const float* __restrict__ wups, const float* __restrict__ bups) {
    int a = blockIdx.z, b = blockIdx.y;
    int gb = a * 2 + b;
    __shared__ float sw[64 * 32];
    __shared__ float sb2[64], sa_[32], sd_[32];
    const float* w   = a ? wups : wup;
    const float* bb  = a ? bups : bup;
    const float* gw  = a ? gnws : gnw;
    const float* gbb = a ? gnbs : gnb;
    double s1 = 0.0, s2 = 0.0;
#pragma unroll
    for (int c = 0; c < 8; c++) { s1 += g_psum[gb][c][0]; s2 += g_psum[gb][c][1]; }
    double mu_d  = s1 / (double)NTOT;
    double var_d = s2 / (double)NTOT - mu_d * mu_d;
    float mu = (float)mu_d;
    float rstd = rsqrtf((float)var_d + 1e-5f);
    for (int i = threadIdx.x; i < 2048; i += 128) sw[i] = w[i];
    if (threadIdx.x < 64) sb2[threadIdx.x] = bb[threadIdx.x];
    if (threadIdx.x < 32) {
        float aa = rstd * gw[threadIdx.x];
        sa_[threadIdx.x] = aa;
        sd_[threadIdx.x] = gbb[threadIdx.x] - mu * aa;
    }
    __syncthreads();
    int p = blockIdx.x * 128 + threadIdx.x;
    const float* src = g_ao[a] + b * 32 * NP;
    float xn[32];
#pragma unroll
    for (int c = 0; c < 32; c++) xn[c] = fmaf(src[c * NP + p], sa_[c], sd_[c]);
    float* dst = g_up[a] + b * 64 * NP;
#pragma unroll
    for (int o = 0; o < 64; o++) {
        float acc = sb2[o];
#pragma unroll
        for (int c = 0; c < 32; c++) acc = fmaf(sw[o * 32 + c], xn[c], acc);
        dst[o * NP + p] = acc;
    }
}

// ---------------- K7: upsample both branches + combine ----------------
__device__ __forceinline__ float tri8(const float* __restrict__ s,
                                      int p00, int p01, int p10, int p11,
                                      int w0, int w1, float ww, float wh, float wt) {
    float c00 = s[p00 + w0]; c00 += (s[p00 + w1] - c00) * ww;
    float c01 = s[p01 + w0]; c01 += (s[p01 + w1] - c01) * ww;
    float c10 = s[p10 + w0]; c10 += (s[p10 + w1] - c10) * ww;
    float c11 = s[p11 + w0]; c11 += (s[p11 + w1] - c11) * ww;
    float c0 = c00 + (c01 - c00) * wh;
    float c1 = c10 + (c11 - c10) * wh;
    return c0 + (c1 - c0) * wt;
}

__global__ void k_final(const float* __restrict__ xc, float* __restrict__ out) {
    int idx = blockIdx.x * 256 + threadIdx.x;          // < 2*64*16*48*48
    int w = idx % WF;
    int h = (idx / WF) % HF;
    int t = (idx / (WF * HF)) % TF;
    int bc = idx / (WF * HF * TF);                     // b*64 + c

    float pt = (float)t * (7.0f / 15.0f);
    int t0 = (int)pt; float wt = pt - (float)t0; int t1 = min(t0 + 1, 7); t0 = min(t0, 7);
    float ph = (float)h * (23.0f / 47.0f);
    int h0 = (int)ph; float wh = ph - (float)h0; int h1 = min(h0 + 1, 23); h0 = min(h0, 23);
    float pw = (float)w * (23.0f / 47.0f);
    int w0 = (int)pw; float ww = pw - (float)w0; int w1 = min(w0 + 1, 23); w0 = min(w0, 23);

    int base = bc * NP;
    int p00 = t0 * (HHd * WWd) + h0 * WWd;
    int p01 = t0 * (HHd * WWd) + h1 * WWd;
    int p10 = t1 * (HHd * WWd) + h0 * WWd;
    int p11 = t1 * (HHd * WWd) + h1 * WWd;

    float r_cross = tri8(g_up[0] + base, p00, p01, p10, p11, w0, w1, ww, wh, wt);
    float r_self  = tri8(g_up[1] + base, p00, p01, p10, p11, w0, w1, ww, wh, wt);
    out[idx] = r_self + xc[idx] - 0.5f * r_cross;
}

// ---------------- launch ----------------
extern "C" void kernel_launch(void* const* d_in, const int* in_sizes, int n_in,
                              void* d_out, int out_size) {
    const float* x       = (const float*)d_in[0];
    const float* x_c     = (const float*)d_in[1];
    const float* w_down  = (const float*)d_in[2];
    const float* b_down  = (const float*)d_in[3];
    const float* w_downc = (const float*)d_in[4];
    const float* b_downc = (const float*)d_in[5];
    const float* w_q     = (const float*)d_in[6];
    const float* b_q     = (const float*)d_in[7];
    const float* w_k     = (const float*)d_in[8];
    const float* b_k     = (const float*)d_in[9];
    const float* w_v     = (const float*)d_in[10];
    const float* b_v     = (const float*)d_in[11];
    const float* w_qsa   = (const float*)d_in[12];
    const float* b_qsa   = (const float*)d_in[13];
    const float* w_ksa   = (const float*)d_in[14];
    const float* b_ksa   = (const float*)d_in[15];
    const float* w_vsa   = (const float*)d_in[16];
    const float* b_vsa   = (const float*)d_in[17];
    const float* gn_w    = (const float*)d_in[18];
    const float* gn_b    = (const float*)d_in[19];
    const float* gn_wsa  = (const float*)d_in[20];
    const float* gn_bsa  = (const float*)d_in[21];
    const float* w_up    = (const float*)d_in[22];
    const float* b_up    = (const float*)d_in[23];
    const float* w_upsa  = (const float*)d_in[24];
    const float* b_upsa  = (const float*)d_in[25];
    const float* offset  = (const float*)d_in[26];
    const float* offsetc = (const float*)d_in[27];

    dim3 g1(2304, 1, 2);
    k_resize<<<g1, 256>>>(x, x_c);

    dim3 g2(72, 1, 2);
    k_down<<<g2, 128>>>(w_down, b_down, w_downc, b_downc);

    k_proj<<<72, 128>>>(w_q, b_q, w_k, b_k, w_v, b_v,
                        w_qsa, b_qsa, w_ksa, b_ksa, w_vsa, b_vsa,
                        offset, offsetc);

    dim3 g4(18, NB, 2 * SPLIT);
    k_attn<<<g4, 128>>>();

    dim3 g4b(36, NB, 2);
    k_attn_red<<<g4b, 128>>>();

    k_stats<<<32, 256>>>();

    dim3 g6(36, NB, 2);
    k_gnup<<<g6, 128>>>(gn_w, gn_b, gn_wsa, gn_bsa, w_up, b_up, w_upsa, b_upsa);

    k_final<<<18432, 256>>>(x_c, (float*)d_out);
}

// round 8
// speedup vs baseline: 2.8714x; 1.6252x over previous
#include <cuda_runtime.h>
#include <cuda_bf16.h>
#include <cstdint>

// ---------------- constants ----------------
#define NB    2
#define CIN   64
#define CD    32
#define HHd   24
#define WWd   24
#define NP    4608          // 8*24*24
#define TF    16
#define HF    48
#define WF    48
#define NTOT  (32*NP)
#define KT    128
#define NKT   (NP/KT)       // 36

// ---------------- scratch ----------------
__device__ float g_xr [NB*CIN*NP];
__device__ float g_xcr[NB*CIN*NP];
__device__ float g_xd [NB*CD*NP];
__device__ float g_xcd[NB*CD*NP];
__device__ __align__(16) __nv_bfloat16 g_qh[2*NB*NP*16];
__device__ __align__(16) __nv_bfloat16 g_ql[2*NB*NP*16];
__device__ __align__(16) __nv_bfloat16 g_kh[2*NB*NP*16];
__device__ __align__(16) __nv_bfloat16 g_kl[2*NB*NP*16];
__device__ __align__(16) __nv_bfloat16 g_vt[2*NB*32*NP];
__device__ float g_ao [2][NB*32*NP];
__device__ float g_up [2][NB*64*NP];
__device__ double g_psum[4][8][2];

// ---------------- helpers ----------------
__device__ __forceinline__ uint32_t pkb(__nv_bfloat16 lo, __nv_bfloat16 hi) {
    return ((uint32_t)__bfloat16_as_ushort(hi) << 16) | (uint32_t)__bfloat16_as_ushort(lo);
}
__device__ __forceinline__ uint32_t pkbf2(float lo, float hi) {
    uint32_t r;
    asm("cvt.rn.bf16x2.f32 %0, %1, %2;" : "=r"(r) : "f"(hi), "f"(lo));
    return r;
}
__device__ __forceinline__ void mma_bf16(float* c, const uint32_t* a, uint32_t b0, uint32_t b1) {
    asm volatile(
        "mma.sync.aligned.m16n8k16.row.col.f32.bf16.bf16.f32 "
        "{%0,%1,%2,%3}, {%4,%5,%6,%7}, {%8,%9}, {%0,%1,%2,%3};"
        : "+f"(c[0]), "+f"(c[1]), "+f"(c[2]), "+f"(c[3])
        : "r"(a[0]), "r"(a[1]), "r"(a[2]), "r"(a[3]), "r"(b0), "r"(b1));
}

// ---------------- K1: trilinear downsample ----------------
__global__ void k_resize(const float* __restrict__ x, const float* __restrict__ xc) {
    int i = blockIdx.x * 256 + threadIdx.x;
    const float* src = blockIdx.z ? xc : x;
    float* dst = blockIdx.z ? g_xcr : g_xr;
    int p  = i % NP;
    int bc = i / NP;
    int w = p % WWd, h = (p / WWd) % HHd, t = p / (WWd * HHd);

    float pt = (float)t * (15.0f / 7.0f);
    int t0 = (int)pt; float wt = pt - (float)t0; int t1 = min(t0 + 1, 15); t0 = min(t0, 15);
    float ph = (float)h * (47.0f / 23.0f);
    int h0 = (int)ph; float wh = ph - (float)h0; int h1 = min(h0 + 1, 47); h0 = min(h0, 47);
    float pw = (float)w * (47.0f / 23.0f);
    int w0 = (int)pw; float ww = pw - (float)w0; int w1 = min(w0 + 1, 47); w0 = min(w0, 47);

    const float* base = src + (size_t)bc * (TF * HF * WF);
#define ATI(ti,hi,wi) __ldg(base + (ti)*(HF*WF) + (hi)*WF + (wi))
    float c00 = ATI(t0,h0,w0); c00 += (ATI(t0,h0,w1) - c00) * ww;
    float c01 = ATI(t0,h1,w0); c01 += (ATI(t0,h1,w1) - c01) * ww;
    float c10 = ATI(t1,h0,w0); c10 += (ATI(t1,h0,w1) - c10) * ww;
    float c11 = ATI(t1,h1,w0); c11 += (ATI(t1,h1,w1) - c11) * ww;
#undef ATI
    float c0 = c00 + (c01 - c00) * wh;
    float c1 = c10 + (c11 - c10) * wh;
    dst[i] = c0 + (c1 - c0) * wt;
}

// ---------------- K2: down conv 64 -> 32 ----------------
__global__ __launch_bounds__(128) void k_down(
    const float* __restrict__ wd, const float* __restrict__ bd,
    const float* __restrict__ wdc, const float* __restrict__ bdc) {
    __shared__ float sw[CD * CIN];
    __shared__ float sb[CD];
    const float* w  = blockIdx.z ? wdc : wd;
    const float* bb = blockIdx.z ? bdc : bd;
    const float* in = blockIdx.z ? g_xcr : g_xr;
    float* out      = blockIdx.z ? g_xcd : g_xd;
    for (int i = threadIdx.x; i < CD * CIN; i += 128) sw[i] = w[i];
    if (threadIdx.x < CD) sb[threadIdx.x] = bb[threadIdx.x];
    __syncthreads();
    int idx = blockIdx.x * 128 + threadIdx.x;
    int b = idx / NP, p = idx % NP;
    float xin[CIN];
#pragma unroll
    for (int c = 0; c < CIN; c++) xin[c] = in[(b * CIN + c) * NP + p];
#pragma unroll
    for (int o = 0; o < CD; o++) {
        float acc = sb[o];
#pragma unroll
        for (int c = 0; c < CIN; c++) acc = fmaf(sw[o * CIN + c], xin[c], acc);
        out[(b * CD + o) * NP + p] = acc;
    }
}

// ---------------- K3: QKV projections + RoPE -> bf16 fragment layouts ----------------
__device__ __forceinline__ void store_hl16(uint32_t* dh, uint32_t* dl, const float* v) {
#pragma unroll
    for (int i = 0; i < 8; i++) {
        float v0 = v[2 * i], v1 = v[2 * i + 1];
        __nv_bfloat16 h0 = __float2bfloat16(v0);
        __nv_bfloat16 h1 = __float2bfloat16(v1);
        __nv_bfloat16 e0 = __float2bfloat16(v0 - __bfloat162float(h0));
        __nv_bfloat16 e1 = __float2bfloat16(v1 - __bfloat162float(h1));
        dh[i] = pkb(h0, h1);
        dl[i] = pkb(e0, e1);
    }
}

__global__ __launch_bounds__(128) void k_proj(
    const float* __restrict__ wq,  const float* __restrict__ bq,
    const float* __restrict__ wk,  const float* __restrict__ bk,
    const float* __restrict__ wv,  const float* __restrict__ bv,
    const float* __restrict__ wqs, const float* __restrict__ bqs,
    const float* __restrict__ wks, const float* __restrict__ bks,
    const float* __restrict__ wvs, const float* __restrict__ bvs,
    const float* __restrict__ off, const float* __restrict__ offc) {
    __shared__ float s_wq[512], s_wk[512], s_wqs[512], s_wks[512];
    __shared__ float s_wv[1024], s_wvs[1024];
    __shared__ float s_bq[16], s_bk[16], s_bqs[16], s_bks[16], s_bv[32], s_bvs[32];
    for (int i = threadIdx.x; i < 512; i += 128) {
        s_wq[i] = wq[i]; s_wk[i] = wk[i]; s_wqs[i] = wqs[i]; s_wks[i] = wks[i];
    }
    for (int i = threadIdx.x; i < 1024; i += 128) { s_wv[i] = wv[i]; s_wvs[i] = wvs[i]; }
    if (threadIdx.x < 16) {
        s_bq[threadIdx.x] = bq[threadIdx.x]; s_bk[threadIdx.x] = bk[threadIdx.x];
        s_bqs[threadIdx.x] = bqs[threadIdx.x]; s_bks[threadIdx.x] = bks[threadIdx.x];
    }
    if (threadIdx.x < 32) { s_bv[threadIdx.x] = bv[threadIdx.x]; s_bvs[threadIdx.x] = bvs[threadIdx.x]; }
    __syncthreads();

    int idx = blockIdx.x * 128 + threadIdx.x;
    int b = idx / NP, p = idx % NP, t = p / (HHd * WWd);

    float xd[32], xcd[32];
#pragma unroll
    for (int c = 0; c < 32; c++) {
        xd[c]  = g_xd [(b * 32 + c) * NP + p];
        xcd[c] = g_xcd[(b * 32 + c) * NP + p];
    }

    const float invf[8] = {1.0f, 0.31622776601683794f, 0.1f, 0.031622776601683794f,
                           0.01f, 0.0031622776601683794f, 0.001f, 0.00031622776601683794f};
    float se[8], ce[8], sc[8], cc[8];
    float tf = (float)t;
#pragma unroll
    for (int i = 0; i < 8; i++) {
        float a = tf * invf[i];
        float s = sinf(a), c = cosf(a);
        float o1 = off[i * 500 + t];
        float o2 = offc[i * 500 + t];
        se[i] = s + o1; ce[i] = c + o1;     // same offset added to sin AND cos (per reference)
        sc[i] = s + o2; cc[i] = c + o2;
    }

    float tmp[16], rv[16];
    int r0 = (0 * NB + b) * NP + p;        // attn 0 row
    int r1 = (1 * NB + b) * NP + p;        // attn 1 row

    // q (attn 0): from xd, rope se/ce, x0.5
#pragma unroll
    for (int o = 0; o < 16; o++) {
        float acc = s_bq[o];
#pragma unroll
        for (int c = 0; c < 32; c++) acc = fmaf(s_wq[o * 32 + c], xd[c], acc);
        tmp[o] = acc;
    }
#pragma unroll
    for (int i = 0; i < 8; i++) {
        rv[i]     = 0.5f * (tmp[i] * ce[i] - tmp[8 + i] * se[i]);
        rv[8 + i] = 0.5f * (tmp[8 + i] * ce[i] + tmp[i] * se[i]);
    }
    store_hl16((uint32_t*)g_qh + r0 * 8, (uint32_t*)g_ql + r0 * 8, rv);

    // k (attn 0): from xcd, rope sc/cc
#pragma unroll
    for (int o = 0; o < 16; o++) {
        float acc = s_bk[o];
#pragma unroll
        for (int c = 0; c < 32; c++) acc = fmaf(s_wk[o * 32 + c], xcd[c], acc);
        tmp[o] = acc;
    }
#pragma unroll
    for (int i = 0; i < 8; i++) {
        rv[i]     = tmp[i] * cc[i] - tmp[8 + i] * sc[i];
        rv[8 + i] = tmp[8 + i] * cc[i] + tmp[i] * sc[i];
    }
    store_hl16((uint32_t*)g_kh + r0 * 8, (uint32_t*)g_kl + r0 * 8, rv);

    // v (attn 0)
#pragma unroll
    for (int o = 0; o < 32; o++) {
        float acc = s_bv[o];
#pragma unroll
        for (int c = 0; c < 32; c++) acc = fmaf(s_wv[o * 32 + c], xcd[c], acc);
        g_vt[((0 * NB + b) * 32 + o) * NP + p] = __float2bfloat16(acc);
    }

    // q_sa (attn 1): from xcd, rope se/ce, x0.5
#pragma unroll
    for (int o = 0; o < 16; o++) {
        float acc = s_bqs[o];
#pragma unroll
        for (int c = 0; c < 32; c++) acc = fmaf(s_wqs[o * 32 + c], xcd[c], acc);
        tmp[o] = acc;
    }
#pragma unroll
    for (int i = 0; i < 8; i++) {
        rv[i]     = 0.5f * (tmp[i] * ce[i] - tmp[8 + i] * se[i]);
        rv[8 + i] = 0.5f * (tmp[8 + i] * ce[i] + tmp[i] * se[i]);
    }
    store_hl16((uint32_t*)g_qh + r1 * 8, (uint32_t*)g_ql + r1 * 8, rv);

    // k_sa (attn 1): from xcd, rope se/ce
#pragma unroll
    for (int o = 0; o < 16; o++) {
        float acc = s_bks[o];
#pragma unroll
        for (int c = 0; c < 32; c++) acc = fmaf(s_wks[o * 32 + c], xcd[c], acc);
        tmp[o] = acc;
    }
#pragma unroll
    for (int i = 0; i < 8; i++) {
        rv[i]     = tmp[i] * ce[i] - tmp[8 + i] * se[i];
        rv[8 + i] = tmp[8 + i] * ce[i] + tmp[i] * se[i];
    }
    store_hl16((uint32_t*)g_kh + r1 * 8, (uint32_t*)g_kl + r1 * 8, rv);

    // v_sa (attn 1)
#pragma unroll
    for (int o = 0; o < 32; o++) {
        float acc = s_bvs[o];
#pragma unroll
        for (int c = 0; c < 32; c++) acc = fmaf(s_wvs[o * 32 + c], xcd[c], acc);
        g_vt[((1 * NB + b) * 32 + o) * NP + p] = __float2bfloat16(acc);
    }
}

// ---------------- K4: FA2-style mma.sync flash attention ----------------
// Warp = 16 queries. S[16x128] = Qhi*Khi + Qhi*Klo + Qlo*Khi (bf16 m16n8k16 MMAs).
// Online softmax in registers; P re-packed C-frag -> A-frag; PV = 8 bf16 MMAs into reg O-acc.
__global__ __launch_bounds__(256) void k_attn() {
    int a = blockIdx.z, b = blockIdx.y;
    int ab = a * NB + b;
    int wid = threadIdx.x >> 5, lane = threadIdx.x & 31;
    int g = lane >> 2, t = lane & 3;
    int q0 = blockIdx.x * 128 + wid * 16;

    const uint32_t* QH = (const uint32_t*)g_qh + (size_t)ab * NP * 8;
    const uint32_t* QL = (const uint32_t*)g_ql + (size_t)ab * NP * 8;
    const uint32_t* KH = (const uint32_t*)g_kh + (size_t)ab * NP * 8;
    const uint32_t* KL = (const uint32_t*)g_kl + (size_t)ab * NP * 8;
    const uint32_t* VT = (const uint32_t*)g_vt + (size_t)ab * 32 * (NP / 2);
    float* O = g_ao[a] + b * 32 * NP;

    uint32_t qh[4], ql[4];
    {
        int r0 = q0 + g, r1 = r0 + 8;
        qh[0] = QH[r0 * 8 + t];     qh[1] = QH[r1 * 8 + t];
        qh[2] = QH[r0 * 8 + t + 4]; qh[3] = QH[r1 * 8 + t + 4];
        ql[0] = QL[r0 * 8 + t];     ql[1] = QL[r1 * 8 + t];
        ql[2] = QL[r0 * 8 + t + 4]; ql[3] = QL[r1 * 8 + t + 4];
    }

    float oacc[16];
#pragma unroll
    for (int i = 0; i < 16; i++) oacc[i] = 0.0f;
    float m0 = -1e30f, m1 = -1e30f, l0 = 0.0f, l1 = 0.0f;

    for (int kt = 0; kt < NKT; kt++) {
        int k0 = kt * KT;
        float acc[16][4];
#pragma unroll
        for (int j = 0; j < 16; j++) {
            acc[j][0] = acc[j][1] = acc[j][2] = acc[j][3] = 0.0f;
        }
#pragma unroll
        for (int j = 0; j < 16; j++) {
            int key = k0 + 8 * j + g;
            uint32_t b0h = __ldg(&KH[key * 8 + t]);
            uint32_t b1h = __ldg(&KH[key * 8 + t + 4]);
            uint32_t b0l = __ldg(&KL[key * 8 + t]);
            uint32_t b1l = __ldg(&KL[key * 8 + t + 4]);
            mma_bf16(acc[j], qh, b0h, b1h);
            mma_bf16(acc[j], ql, b0h, b1h);
            mma_bf16(acc[j], qh, b0l, b1l);
        }
        // row maxes (row g -> c0,c1 ; row g+8 -> c2,c3)
        float mr0 = -1e30f, mr1 = -1e30f;
#pragma unroll
        for (int j = 0; j < 16; j++) {
            mr0 = fmaxf(mr0, fmaxf(acc[j][0], acc[j][1]));
            mr1 = fmaxf(mr1, fmaxf(acc[j][2], acc[j][3]));
        }
        mr0 = fmaxf(mr0, __shfl_xor_sync(0xffffffffu, mr0, 1));
        mr0 = fmaxf(mr0, __shfl_xor_sync(0xffffffffu, mr0, 2));
        mr1 = fmaxf(mr1, __shfl_xor_sync(0xffffffffu, mr1, 1));
        mr1 = fmaxf(mr1, __shfl_xor_sync(0xffffffffu, mr1, 2));
        float m0n = fmaxf(m0, mr0), m1n = fmaxf(m1, mr1);
        float c0 = __expf(m0 - m0n), c1 = __expf(m1 - m1n);
#pragma unroll
        for (int i = 0; i < 16; i++) oacc[i] *= ((i & 2) ? c1 : c0);
        l0 *= c0; l1 *= c1;
        m0 = m0n; m1 = m1n;

        float ls0 = 0.0f, ls1 = 0.0f;
#pragma unroll
        for (int kc = 0; kc < 8; kc++) {
            float p0 = __expf(acc[2 * kc][0] - m0);
            float p1 = __expf(acc[2 * kc][1] - m0);
            float p2 = __expf(acc[2 * kc][2] - m1);
            float p3 = __expf(acc[2 * kc][3] - m1);
            float p4 = __expf(acc[2 * kc + 1][0] - m0);
            float p5 = __expf(acc[2 * kc + 1][1] - m0);
            float p6 = __expf(acc[2 * kc + 1][2] - m1);
            float p7 = __expf(acc[2 * kc + 1][3] - m1);
            ls0 += (p0 + p1) + (p4 + p5);
            ls1 += (p2 + p3) + (p6 + p7);
            uint32_t pa[4] = { pkbf2(p0, p1), pkbf2(p2, p3), pkbf2(p4, p5), pkbf2(p6, p7) };
            int kv = (k0 + 16 * kc) / 2 + t;
#pragma unroll
            for (int j2 = 0; j2 < 4; j2++) {
                const uint32_t* vr = VT + (8 * j2 + g) * (NP / 2);
                uint32_t vb0 = __ldg(&vr[kv]);
                uint32_t vb1 = __ldg(&vr[kv + 4]);
                mma_bf16(&oacc[4 * j2], pa, vb0, vb1);
            }
        }
        ls0 += __shfl_xor_sync(0xffffffffu, ls0, 1);
        ls0 += __shfl_xor_sync(0xffffffffu, ls0, 2);
        ls1 += __shfl_xor_sync(0xffffffffu, ls1, 1);
        ls1 += __shfl_xor_sync(0xffffffffu, ls1, 2);
        l0 += ls0; l1 += ls1;
    }

    float inv0 = 1.0f / l0, inv1 = 1.0f / l1;
    int r0 = q0 + g, r1 = r0 + 8;
#pragma unroll
    for (int j2 = 0; j2 < 4; j2++) {
        int ch = 8 * j2 + 2 * t;
        O[ch * NP + r0]       = oacc[4 * j2 + 0] * inv0;
        O[(ch + 1) * NP + r0] = oacc[4 * j2 + 1] * inv0;
        O[ch * NP + r1]       = oacc[4 * j2 + 2] * inv1;
        O[(ch + 1) * NP + r1] = oacc[4 * j2 + 3] * inv1;
    }
}

// ---------------- K5: groupnorm partial stats ----------------
__global__ __launch_bounds__(256) void k_stats() {
    int gb = blockIdx.x >> 3;
    int ch = blockIdx.x & 7;
    int aa = gb >> 1, b = gb & 1;
    const float* src = g_ao[aa] + b * 32 * NP + ch * (NTOT / 8);
    float s1 = 0.0f;
    double s2 = 0.0;
    for (int i = threadIdx.x; i < NTOT / 8; i += 256) {
        float v = src[i];
        s1 += v;
        s2 += (double)v * (double)v;
    }
    __shared__ float  r1[256];
    __shared__ double r2[256];
    r1[threadIdx.x] = s1; r2[threadIdx.x] = s2;
    __syncthreads();
    for (int s = 128; s > 0; s >>= 1) {
        if (threadIdx.x < s) { r1[threadIdx.x] += r1[threadIdx.x + s]; r2[threadIdx.x] += r2[threadIdx.x + s]; }
        __syncthreads();
    }
    if (threadIdx.x == 0) {
        g_psum[gb][ch][0] = (double)r1[0];
        g_psum[gb][ch][1] = r2[0];
    }
}

// ---------------- K6: groupnorm apply + up conv 32 -> 64 ----------------
__global__ __launch_bounds__(128) void k_gnup(
    const float* __restrict__ gnw,  const float* __restrict__ gnb,
    const float* __restrict__ gnws, const float* __restrict__ gnbs,
    const float* __restrict__ wup,  const float* __restrict__ bup,
    const float* __restrict__ wups, const float* __restrict__ bups) {
    int a = blockIdx.z, b = blockIdx.y;
    int gb = a * 2 + b;
    __shared__ float sw[64 * 32];
    __shared__ float sb2[64], sa_[32], sd_[32];
    const float* w   = a ? wups : wup;
    const float* bb  = a ? bups : bup;
    const float* gw  = a ? gnws : gnw;
    const float* gbb = a ? gnbs : gnb;
    double s1 = 0.0, s2 = 0.0;
#pragma unroll
    for (int c = 0; c < 8; c++) { s1 += g_psum[gb][c][0]; s2 += g_psum[gb][c][1]; }
    double mu_d  = s1 / (double)NTOT;
    double var_d = s2 / (double)NTOT - mu_d * mu_d;
    float mu = (float)mu_d;
    float rstd = rsqrtf((float)var_d + 1e-5f);
    for (int i = threadIdx.x; i < 2048; i += 128) sw[i] = w[i];
    if (threadIdx.x < 64) sb2[threadIdx.x] = bb[threadIdx.x];
    if (threadIdx.x < 32) {
        float aa = rstd * gw[threadIdx.x];
        sa_[threadIdx.x] = aa;
        sd_[threadIdx.x] = gbb[threadIdx.x] - mu * aa;
    }
    __syncthreads();
    int p = blockIdx.x * 128 + threadIdx.x;
    const float* src = g_ao[a] + b * 32 * NP;
    float xn[32];
#pragma unroll
    for (int c = 0; c < 32; c++) xn[c] = fmaf(src[c * NP + p], sa_[c], sd_[c]);
    float* dst = g_up[a] + b * 64 * NP;
#pragma unroll
    for (int o = 0; o < 64; o++) {
        float acc = sb2[o];
#pragma unroll
        for (int c = 0; c < 32; c++) acc = fmaf(sw[o * 32 + c], xn[c], acc);
        dst[o * NP + p] = acc;
    }
}

// ---------------- K7: upsample + combine ----------------
__device__ __forceinline__ float tri8(const float* __restrict__ s,
                                      int p00, int p01, int p10, int p11,
                                      int w0, int w1, float ww, float wh, float wt) {
    float c00 = s[p00 + w0]; c00 += (s[p00 + w1] - c00) * ww;
    float c01 = s[p01 + w0]; c01 += (s[p01 + w1] - c01) * ww;
    float c10 = s[p10 + w0]; c10 += (s[p10 + w1] - c10) * ww;
    float c11 = s[p11 + w0]; c11 += (s[p11 + w1] - c11) * ww;
    float c0 = c00 + (c01 - c00) * wh;
    float c1 = c10 + (c11 - c10) * wh;
    return c0 + (c1 - c0) * wt;
}

__global__ void k_final(const float* __restrict__ xc, float* __restrict__ out) {
    int idx = blockIdx.x * 256 + threadIdx.x;
    int w = idx % WF;
    int h = (idx / WF) % HF;
    int t = (idx / (WF * HF)) % TF;
    int bc = idx / (WF * HF * TF);

    float pt = (float)t * (7.0f / 15.0f);
    int t0 = (int)pt; float wt = pt - (float)t0; int t1 = min(t0 + 1, 7); t0 = min(t0, 7);
    float ph = (float)h * (23.0f / 47.0f);
    int h0 = (int)ph; float wh = ph - (float)h0; int h1 = min(h0 + 1, 23); h0 = min(h0, 23);
    float pw = (float)w * (23.0f / 47.0f);
    int w0 = (int)pw; float ww = pw - (float)w0; int w1 = min(w0 + 1, 23); w0 = min(w0, 23);

    int base = bc * NP;
    int p00 = t0 * (HHd * WWd) + h0 * WWd;
    int p01 = t0 * (HHd * WWd) + h1 * WWd;
    int p10 = t1 * (HHd * WWd) + h0 * WWd;
    int p11 = t1 * (HHd * WWd) + h1 * WWd;

    float r_cross = tri8(g_up[0] + base, p00, p01, p10, p11, w0, w1, ww, wh, wt);
    float r_self  = tri8(g_up[1] + base, p00, p01, p10, p11, w0, w1, ww, wh, wt);
    out[idx] = r_self + xc[idx] - 0.5f * r_cross;
}

// ---------------- launch ----------------
extern "C" void kernel_launch(void* const* d_in, const int* in_sizes, int n_in,
                              void* d_out, int out_size) {
    const float* x       = (const float*)d_in[0];
    const float* x_c     = (const float*)d_in[1];
    const float* w_down  = (const float*)d_in[2];
    const float* b_down  = (const float*)d_in[3];
    const float* w_downc = (const float*)d_in[4];
    const float* b_downc = (const float*)d_in[5];
    const float* w_q     = (const float*)d_in[6];
    const float* b_q     = (const float*)d_in[7];
    const float* w_k     = (const float*)d_in[8];
    const float* b_k     = (const float*)d_in[9];
    const float* w_v     = (const float*)d_in[10];
    const float* b_v     = (const float*)d_in[11];
    const float* w_qsa   = (const float*)d_in[12];
    const float* b_qsa   = (const float*)d_in[13];
    const float* w_ksa   = (const float*)d_in[14];
    const float* b_ksa   = (const float*)d_in[15];
    const float* w_vsa   = (const float*)d_in[16];
    const float* b_vsa   = (const float*)d_in[17];
    const float* gn_w    = (const float*)d_in[18];
    const float* gn_b    = (const float*)d_in[19];
    const float* gn_wsa  = (const float*)d_in[20];
    const float* gn_bsa  = (const float*)d_in[21];
    const float* w_up    = (const float*)d_in[22];
    const float* b_up    = (const float*)d_in[23];
    const float* w_upsa  = (const float*)d_in[24];
    const float* b_upsa  = (const float*)d_in[25];
    const float* offset  = (const float*)d_in[26];
    const float* offsetc = (const float*)d_in[27];

    dim3 g1(2304, 1, 2);
    k_resize<<<g1, 256>>>(x, x_c);

    dim3 g2(72, 1, 2);
    k_down<<<g2, 128>>>(w_down, b_down, w_downc, b_downc);

    k_proj<<<72, 128>>>(w_q, b_q, w_k, b_k, w_v, b_v,
                        w_qsa, b_qsa, w_ksa, b_ksa, w_vsa, b_vsa,
                        offset, offsetc);

    dim3 g4(36, NB, 2);
    k_attn<<<g4, 256>>>();

    k_stats<<<32, 256>>>();

    dim3 g6(36, NB, 2);
    k_gnup<<<g6, 128>>>(gn_w, gn_b, gn_wsa, gn_bsa, w_up, b_up, w_upsa, b_upsa);

    k_final<<<18432, 256>>>(x_c, (float*)d_out);
}

// round 9
// speedup vs baseline: 4.2513x; 1.4806x over previous
#include <cuda_runtime.h>
#include <cuda_bf16.h>
#include <cstdint>

// ---------------- constants ----------------
#define NB    2
#define CIN   64
#define CD    32
#define HHd   24
#define WWd   24
#define NP    4608          // 8*24*24
#define TF    16
#define HF    48
#define WF    48
#define NTOT  (32*NP)
#define KT    128
#define NKT   (NP/KT)       // 36

typedef unsigned long long u64;

// ---------------- scratch ----------------
__device__ float g_xr [NB*CIN*NP];
__device__ float g_xcr[NB*CIN*NP];
__device__ float g_xd [NB*CD*NP];
__device__ float g_xcd[NB*CD*NP];
// Q/K: per row 8 u64 slots; slot s = {lo32: bf16x2 hi-pair(ch 2s,2s+1), hi32: bf16x2 lo-pair}
__device__ __align__(16) u64 g_qhl[2*NB*NP*8];
__device__ __align__(16) u64 g_khl[2*NB*NP*8];
// V: per (ab,ch): NP/16 groups x 32B; group block: slot t(8B) = {pair(16g+2t,+1), pair(16g+2t+8,+9)}
__device__ __align__(16) char g_vp[(size_t)2*NB*32*NP*2];
__device__ float g_ao [2][NB*32*NP];
__device__ float g_up [2][NB*64*NP];
__device__ double g_psum[4][8][2];

// ---------------- helpers ----------------
__device__ __forceinline__ uint32_t smem_u32(const void* p) {
    uint32_t a;
    asm("{ .reg .u64 t; cvta.to.shared.u64 t, %1; cvt.u32.u64 %0, t; }" : "=r"(a) : "l"(p));
    return a;
}
__device__ __forceinline__ uint32_t pkb(__nv_bfloat16 lo, __nv_bfloat16 hi) {
    return ((uint32_t)__bfloat16_as_ushort(hi) << 16) | (uint32_t)__bfloat16_as_ushort(lo);
}
__device__ __forceinline__ uint32_t pkbf2(float lo, float hi) {
    uint32_t r;
    asm("cvt.rn.bf16x2.f32 %0, %1, %2;" : "=r"(r) : "f"(hi), "f"(lo));
    return r;
}
__device__ __forceinline__ void mma_bf16(float* c, const uint32_t* a, uint32_t b0, uint32_t b1) {
    asm volatile(
        "mma.sync.aligned.m16n8k16.row.col.f32.bf16.bf16.f32 "
        "{%0,%1,%2,%3}, {%4,%5,%6,%7}, {%8,%9}, {%0,%1,%2,%3};"
        : "+f"(c[0]), "+f"(c[1]), "+f"(c[2]), "+f"(c[3])
        : "r"(a[0]), "r"(a[1]), "r"(a[2]), "r"(a[3]), "r"(b0), "r"(b1));
}
__device__ __forceinline__ void cpa16(uint32_t dst, const void* src) {
    asm volatile("cp.async.cg.shared.global [%0], [%1], 16;" :: "r"(dst), "l"(src) : "memory");
}
#define CP_COMMIT() asm volatile("cp.async.commit_group;" ::: "memory")
#define CP_WAIT1()  asm volatile("cp.async.wait_group 1;" ::: "memory")
#define CP_WAIT0()  asm volatile("cp.async.wait_group 0;" ::: "memory")

// ---------------- K1: trilinear downsample ----------------
__global__ void k_resize(const float* __restrict__ x, const float* __restrict__ xc) {
    int i = blockIdx.x * 256 + threadIdx.x;
    const float* src = blockIdx.z ? xc : x;
    float* dst = blockIdx.z ? g_xcr : g_xr;
    int p  = i % NP;
    int bc = i / NP;
    int w = p % WWd, h = (p / WWd) % HHd, t = p / (WWd * HHd);

    float pt = (float)t * (15.0f / 7.0f);
    int t0 = (int)pt; float wt = pt - (float)t0; int t1 = min(t0 + 1, 15); t0 = min(t0, 15);
    float ph = (float)h * (47.0f / 23.0f);
    int h0 = (int)ph; float wh = ph - (float)h0; int h1 = min(h0 + 1, 47); h0 = min(h0, 47);
    float pw = (float)w * (47.0f / 23.0f);
    int w0 = (int)pw; float ww = pw - (float)w0; int w1 = min(w0 + 1, 47); w0 = min(w0, 47);

    const float* base = src + (size_t)bc * (TF * HF * WF);
#define ATI(ti,hi,wi) __ldg(base + (ti)*(HF*WF) + (hi)*WF + (wi))
    float c00 = ATI(t0,h0,w0); c00 += (ATI(t0,h0,w1) - c00) * ww;
    float c01 = ATI(t0,h1,w0); c01 += (ATI(t0,h1,w1) - c01) * ww;
    float c10 = ATI(t1,h0,w0); c10 += (ATI(t1,h0,w1) - c10) * ww;
    float c11 = ATI(t1,h1,w0); c11 += (ATI(t1,h1,w1) - c11) * ww;
#undef ATI
    float c0 = c00 + (c01 - c00) * wh;
    float c1 = c10 + (c11 - c10) * wh;
    dst[i] = c0 + (c1 - c0) * wt;
}

// ---------------- K2: down conv 64 -> 32 ----------------
__global__ __launch_bounds__(128) void k_down(
    const float* __restrict__ wd, const float* __restrict__ bd,
    const float* __restrict__ wdc, const float* __restrict__ bdc) {
    __shared__ float sw[CD * CIN];
    __shared__ float sb[CD];
    const float* w  = blockIdx.z ? wdc : wd;
    const float* bb = blockIdx.z ? bdc : bd;
    const float* in = blockIdx.z ? g_xcr : g_xr;
    float* out      = blockIdx.z ? g_xcd : g_xd;
    for (int i = threadIdx.x; i < CD * CIN; i += 128) sw[i] = w[i];
    if (threadIdx.x < CD) sb[threadIdx.x] = bb[threadIdx.x];
    __syncthreads();
    int idx = blockIdx.x * 128 + threadIdx.x;
    int b = idx / NP, p = idx % NP;
    float xin[CIN];
#pragma unroll
    for (int c = 0; c < CIN; c++) xin[c] = in[(b * CIN + c) * NP + p];
#pragma unroll
    for (int o = 0; o < CD; o++) {
        float acc = sb[o];
#pragma unroll
        for (int c = 0; c < CIN; c++) acc = fmaf(sw[o * CIN + c], xin[c], acc);
        out[(b * CD + o) * NP + p] = acc;
    }
}

// ---------------- K3: QKV projections + RoPE -> packed layouts ----------------
__device__ __forceinline__ void store_hl16i(u64* d, const float* v) {
#pragma unroll
    for (int i = 0; i < 8; i++) {
        float v0 = v[2 * i], v1 = v[2 * i + 1];
        __nv_bfloat16 h0 = __float2bfloat16(v0);
        __nv_bfloat16 h1 = __float2bfloat16(v1);
        __nv_bfloat16 e0 = __float2bfloat16(v0 - __bfloat162float(h0));
        __nv_bfloat16 e1 = __float2bfloat16(v1 - __bfloat162float(h1));
        d[i] = ((u64)pkb(e0, e1) << 32) | (u64)pkb(h0, h1);
    }
}
__device__ __forceinline__ void store_v(char* base_ab_ch, int p, float val) {
    int gi = p >> 4, r = p & 15;
    int ofs = ((r & 7) >> 1) * 8 + ((r >> 3) & 1) * 4 + (r & 1) * 2;
    *(__nv_bfloat16*)(base_ab_ch + (size_t)gi * 32 + ofs) = __float2bfloat16(val);
}

// z = 0: q,k,v (attn 0) ; z = 1: q_sa,k_sa,v_sa (attn 1)
__global__ __launch_bounds__(128) void k_proj(
    const float* __restrict__ wq,  const float* __restrict__ bq,
    const float* __restrict__ wk,  const float* __restrict__ bk,
    const float* __restrict__ wv,  const float* __restrict__ bv,
    const float* __restrict__ wqs, const float* __restrict__ bqs,
    const float* __restrict__ wks, const float* __restrict__ bks,
    const float* __restrict__ wvs, const float* __restrict__ bvs,
    const float* __restrict__ off, const float* __restrict__ offc) {
    int z = blockIdx.z;
    __shared__ float s_wq[512], s_wk[512], s_wv[1024];
    __shared__ float s_bq[16], s_bk[16], s_bv[32];
    {
        const float* WQ = z ? wqs : wq;
        const float* WK = z ? wks : wk;
        const float* WV = z ? wvs : wv;
        const float* BQ = z ? bqs : bq;
        const float* BK = z ? bks : bk;
        const float* BV = z ? bvs : bv;
        for (int i = threadIdx.x; i < 512; i += 128) { s_wq[i] = WQ[i]; s_wk[i] = WK[i]; }
        for (int i = threadIdx.x; i < 1024; i += 128) s_wv[i] = WV[i];
        if (threadIdx.x < 16) { s_bq[threadIdx.x] = BQ[threadIdx.x]; s_bk[threadIdx.x] = BK[threadIdx.x]; }
        if (threadIdx.x < 32) s_bv[threadIdx.x] = BV[threadIdx.x];
    }
    __syncthreads();

    int idx = blockIdx.x * 128 + threadIdx.x;
    int b = idx / NP, p = idx % NP, t = p / (HHd * WWd);
    int ab = z * NB + b;

    float xq[32], xcd[32];
#pragma unroll
    for (int c = 0; c < 32; c++) xcd[c] = g_xcd[(b * 32 + c) * NP + p];
    if (z == 0) {
#pragma unroll
        for (int c = 0; c < 32; c++) xq[c] = g_xd[(b * 32 + c) * NP + p];
    } else {
#pragma unroll
        for (int c = 0; c < 32; c++) xq[c] = xcd[c];
    }

    const float invf[8] = {1.0f, 0.31622776601683794f, 0.1f, 0.031622776601683794f,
                           0.01f, 0.0031622776601683794f, 0.001f, 0.00031622776601683794f};
    float se[8], ce[8], sk_[8], ck_[8];
    float tf = (float)t;
#pragma unroll
    for (int i = 0; i < 8; i++) {
        float a = tf * invf[i];
        float s = sinf(a), c = cosf(a);
        float o1 = off[i * 500 + t];             // q rope offset (both attns use `offset`)
        se[i] = s + o1; ce[i] = c + o1;          // same offset on sin AND cos (per reference)
        if (z == 0) {
            float o2 = offc[i * 500 + t];        // cross-attn k uses offset_c
            sk_[i] = s + o2; ck_[i] = c + o2;
        } else {
            sk_[i] = se[i]; ck_[i] = ce[i];      // self-attn k uses offset
        }
    }

    float tmp[16], rv[16];
    int row = ab * NP + p;

    // q = rope(Wq*xq + bq) * 0.5
#pragma unroll
    for (int o = 0; o < 16; o++) {
        float acc = s_bq[o];
#pragma unroll
        for (int c = 0; c < 32; c++) acc = fmaf(s_wq[o * 32 + c], xq[c], acc);
        tmp[o] = acc;
    }
#pragma unroll
    for (int i = 0; i < 8; i++) {
        rv[i]     = 0.5f * (tmp[i] * ce[i] - tmp[8 + i] * se[i]);
        rv[8 + i] = 0.5f * (tmp[8 + i] * ce[i] + tmp[i] * se[i]);
    }
    store_hl16i(g_qhl + (size_t)row * 8, rv);

    // k = rope(Wk*xcd + bk)
#pragma unroll
    for (int o = 0; o < 16; o++) {
        float acc = s_bk[o];
#pragma unroll
        for (int c = 0; c < 32; c++) acc = fmaf(s_wk[o * 32 + c], xcd[c], acc);
        tmp[o] = acc;
    }
#pragma unroll
    for (int i = 0; i < 8; i++) {
        rv[i]     = tmp[i] * ck_[i] - tmp[8 + i] * sk_[i];
        rv[8 + i] = tmp[8 + i] * ck_[i] + tmp[i] * sk_[i];
    }
    store_hl16i(g_khl + (size_t)row * 8, rv);

    // v
#pragma unroll
    for (int o = 0; o < 32; o++) {
        float acc = s_bv[o];
#pragma unroll
        for (int c = 0; c < 32; c++) acc = fmaf(s_wv[o * 32 + c], xcd[c], acc);
        store_v(g_vp + (size_t)(ab * 32 + o) * (NP * 2), p, acc);
    }
}

// ---------------- K4: smem-staged, double-buffered FA2 mma.sync attention ----------------
__device__ __forceinline__ void stage_tile(const char* gk, const char* gv,
                                           uint32_t skb, uint32_t svb,
                                           int tid, int tile, int buf) {
    const char* ks = gk + (size_t)tile * 8192;
    uint32_t kd = skb + (uint32_t)buf * 8192;
#pragma unroll
    for (int n = 0; n < 4; n++) {
        uint32_t off = (uint32_t)(tid + n * 128) * 16;
        uint32_t key = off >> 6;
        cpa16(kd + (off ^ ((key & 3) << 5)), ks + off);
    }
    const char* vs = gv + (size_t)tile * 256;
    uint32_t vd = svb + (uint32_t)buf * 8192;
#pragma unroll
    for (int n = 0; n < 4; n++) {
        int w = tid + n * 128;
        int ch = w >> 4, wi = w & 15;
        uint32_t off = (uint32_t)(ch * 256 + wi * 16);
        cpa16(vd + (off ^ (((uint32_t)ch & 3) << 5)), vs + (size_t)ch * (NP * 2) + wi * 16);
    }
}

__global__ __launch_bounds__(128) void k_attn() {
    __shared__ __align__(128) char sKs[2][8192];
    __shared__ __align__(128) char sVs[2][8192];
    int a = blockIdx.z, b = blockIdx.y;
    int ab = a * NB + b;
    int tid = threadIdx.x;
    int wid = tid >> 5, lane = tid & 31;
    int g = lane >> 2, t = lane & 3;
    int q0 = blockIdx.x * 64 + wid * 16;

    const u64* QHL = g_qhl + (size_t)ab * NP * 8;
    const char* gk = (const char*)(g_khl + (size_t)ab * NP * 8);
    const char* gv = g_vp + (size_t)ab * 32 * (NP * 2);
    float* O = g_ao[a] + b * 32 * NP;

    uint32_t skb = smem_u32(sKs);
    uint32_t svb = smem_u32(sVs);
    uint32_t swz = ((uint32_t)g & 3) << 5;

    uint32_t qh[4], ql[4];
    {
        int r0 = q0 + g, r1 = r0 + 8;
        u64 w0 = QHL[r0 * 8 + t];
        u64 w1 = QHL[r1 * 8 + t];
        u64 w2 = QHL[r0 * 8 + t + 4];
        u64 w3 = QHL[r1 * 8 + t + 4];
        qh[0] = (uint32_t)w0; ql[0] = (uint32_t)(w0 >> 32);
        qh[1] = (uint32_t)w1; ql[1] = (uint32_t)(w1 >> 32);
        qh[2] = (uint32_t)w2; ql[2] = (uint32_t)(w2 >> 32);
        qh[3] = (uint32_t)w3; ql[3] = (uint32_t)(w3 >> 32);
    }

    float oacc[16];
#pragma unroll
    for (int i = 0; i < 16; i++) oacc[i] = 0.0f;
    float m0 = -1e30f, m1 = -1e30f, l0 = 0.0f, l1 = 0.0f;

    stage_tile(gk, gv, skb, svb, tid, 0, 0);
    CP_COMMIT();

    for (int kt = 0; kt < NKT; kt++) {
        int buf = kt & 1;
        if (kt + 1 < NKT) {
            stage_tile(gk, gv, skb, svb, tid, kt + 1, (kt + 1) & 1);
            CP_COMMIT();
            CP_WAIT1();
        } else {
            CP_WAIT0();
        }
        __syncthreads();

        uint32_t kb = skb + (uint32_t)buf * 8192;
        uint32_t vbb = svb + (uint32_t)buf * 8192;

        float acc[16][4];
#pragma unroll
        for (int j = 0; j < 16; j++) {
            acc[j][0] = acc[j][1] = acc[j][2] = acc[j][3] = 0.0f;
        }
#pragma unroll
        for (int j = 0; j < 16; j++) {
            uint32_t row = (uint32_t)(8 * j + g) * 64 + (uint32_t)t * 8;
            uint32_t a0 = kb + (row ^ swz);
            uint32_t a1 = kb + ((row + 32) ^ swz);
            uint32_t b0h, b0l, b1h, b1l;
            asm("ld.shared.v2.b32 {%0,%1}, [%2];" : "=r"(b0h), "=r"(b0l) : "r"(a0));
            asm("ld.shared.v2.b32 {%0,%1}, [%2];" : "=r"(b1h), "=r"(b1l) : "r"(a1));
            mma_bf16(acc[j], qh, b0h, b1h);
            mma_bf16(acc[j], ql, b0h, b1h);
            mma_bf16(acc[j], qh, b0l, b1l);
        }

        float mr0 = -1e30f, mr1 = -1e30f;
#pragma unroll
        for (int j = 0; j < 16; j++) {
            mr0 = fmaxf(mr0, fmaxf(acc[j][0], acc[j][1]));
            mr1 = fmaxf(mr1, fmaxf(acc[j][2], acc[j][3]));
        }
        mr0 = fmaxf(mr0, __shfl_xor_sync(0xffffffffu, mr0, 1));
        mr0 = fmaxf(mr0, __shfl_xor_sync(0xffffffffu, mr0, 2));
        mr1 = fmaxf(mr1, __shfl_xor_sync(0xffffffffu, mr1, 1));
        mr1 = fmaxf(mr1, __shfl_xor_sync(0xffffffffu, mr1, 2));
        float m0n = fmaxf(m0, mr0), m1n = fmaxf(m1, mr1);
        float c0 = __expf(m0 - m0n), c1 = __expf(m1 - m1n);
#pragma unroll
        for (int i = 0; i < 16; i++) oacc[i] *= ((i & 2) ? c1 : c0);
        l0 *= c0; l1 *= c1;
        m0 = m0n; m1 = m1n;

        float ls0 = 0.0f, ls1 = 0.0f;
#pragma unroll
        for (int kc = 0; kc < 8; kc++) {
            float p0 = __expf(acc[2 * kc][0] - m0);
            float p1 = __expf(acc[2 * kc][1] - m0);
            float p2 = __expf(acc[2 * kc][2] - m1);
            float p3 = __expf(acc[2 * kc][3] - m1);
            float p4 = __expf(acc[2 * kc + 1][0] - m0);
            float p5 = __expf(acc[2 * kc + 1][1] - m0);
            float p6 = __expf(acc[2 * kc + 1][2] - m1);
            float p7 = __expf(acc[2 * kc + 1][3] - m1);
            ls0 += (p0 + p1) + (p4 + p5);
            ls1 += (p2 + p3) + (p6 + p7);
            uint32_t pa[4] = { pkbf2(p0, p1), pkbf2(p2, p3), pkbf2(p4, p5), pkbf2(p6, p7) };
#pragma unroll
            for (int j2 = 0; j2 < 4; j2++) {
                uint32_t off = (uint32_t)((8 * j2 + g) * 256 + kc * 32 + t * 8);
                uint32_t addr = vbb + (off ^ swz);
                uint32_t vb0, vb1;
                asm("ld.shared.v2.b32 {%0,%1}, [%2];" : "=r"(vb0), "=r"(vb1) : "r"(addr));
                mma_bf16(&oacc[4 * j2], pa, vb0, vb1);
            }
        }
        ls0 += __shfl_xor_sync(0xffffffffu, ls0, 1);
        ls0 += __shfl_xor_sync(0xffffffffu, ls0, 2);
        ls1 += __shfl_xor_sync(0xffffffffu, ls1, 1);
        ls1 += __shfl_xor_sync(0xffffffffu, ls1, 2);
        l0 += ls0; l1 += ls1;

        __syncthreads();
    }

    float inv0 = 1.0f / l0, inv1 = 1.0f / l1;
    int r0 = q0 + g, r1 = r0 + 8;
#pragma unroll
    for (int j2 = 0; j2 < 4; j2++) {
        int ch = 8 * j2 + 2 * t;
        O[ch * NP + r0]       = oacc[4 * j2 + 0] * inv0;
        O[(ch + 1) * NP + r0] = oacc[4 * j2 + 1] * inv0;
        O[ch * NP + r1]       = oacc[4 * j2 + 2] * inv1;
        O[(ch + 1) * NP + r1] = oacc[4 * j2 + 3] * inv1;
    }
}

// ---------------- K5: groupnorm partial stats ----------------
__global__ __launch_bounds__(256) void k_stats() {
    int gb = blockIdx.x >> 3;
    int ch = blockIdx.x & 7;
    int aa = gb >> 1, b = gb & 1;
    const float* src = g_ao[aa] + b * 32 * NP + ch * (NTOT / 8);
    float s1 = 0.0f;
    double s2 = 0.0;
    for (int i = threadIdx.x; i < NTOT / 8; i += 256) {
        float v = src[i];
        s1 += v;
        s2 += (double)v * (double)v;
    }
    __shared__ float  r1[256];
    __shared__ double r2[256];
    r1[threadIdx.x] = s1; r2[threadIdx.x] = s2;
    __syncthreads();
    for (int s = 128; s > 0; s >>= 1) {
        if (threadIdx.x < s) { r1[threadIdx.x] += r1[threadIdx.x + s]; r2[threadIdx.x] += r2[threadIdx.x + s]; }
        __syncthreads();
    }
    if (threadIdx.x == 0) {
        g_psum[gb][ch][0] = (double)r1[0];
        g_psum[gb][ch][1] = r2[0];
    }
}

// ---------------- K6: groupnorm apply + up conv 32 -> 64 ----------------
__global__ __launch_bounds__(128) void k_gnup(
    const float* __restrict__ gnw,  const float* __restrict__ gnb,
    const float* __restrict__ gnws, const float* __restrict__ gnbs,
    const float* __restrict__ wup,  const float* __restrict__ bup,
    const float* __restrict__ wups, const float* __restrict__ bups) {
    int a = blockIdx.z, b = blockIdx.y;
    int gb = a * 2 + b;
    __shared__ float sw[64 * 32];
    __shared__ float sb2[64], sa_[32], sd_[32];
    const float* w   = a ? wups : wup;
    const float* bb  = a ? bups : bup;
    const float* gw  = a ? gnws : gnw;
    const float* gbb = a ? gnbs : gnb;
    double s1 = 0.0, s2 = 0.0;
#pragma unroll
    for (int c = 0; c < 8; c++) { s1 += g_psum[gb][c][0]; s2 += g_psum[gb][c][1]; }
    double mu_d  = s1 / (double)NTOT;
    double var_d = s2 / (double)NTOT - mu_d * mu_d;
    float mu = (float)mu_d;
    float rstd = rsqrtf((float)var_d + 1e-5f);
    for (int i = threadIdx.x; i < 2048; i += 128) sw[i] = w[i];
    if (threadIdx.x < 64) sb2[threadIdx.x] = bb[threadIdx.x];
    if (threadIdx.x < 32) {
        float aa = rstd * gw[threadIdx.x];
        sa_[threadIdx.x] = aa;
        sd_[threadIdx.x] = gbb[threadIdx.x] - mu * aa;
    }
    __syncthreads();
    int p = blockIdx.x * 128 + threadIdx.x;
    const float* src = g_ao[a] + b * 32 * NP;
    float xn[32];
#pragma unroll
    for (int c = 0; c < 32; c++) xn[c] = fmaf(src[c * NP + p], sa_[c], sd_[c]);
    float* dst = g_up[a] + b * 64 * NP;
#pragma unroll
    for (int o = 0; o < 64; o++) {
        float acc = sb2[o];
#pragma unroll
        for (int c = 0; c < 32; c++) acc = fmaf(sw[o * 32 + c], xn[c], acc);
        dst[o * NP + p] = acc;
    }
}

// ---------------- K7: upsample + combine ----------------
__device__ __forceinline__ float tri8(const float* __restrict__ s,
                                      int p00, int p01, int p10, int p11,
                                      int w0, int w1, float ww, float wh, float wt) {
    float c00 = s[p00 + w0]; c00 += (s[p00 + w1] - c00) * ww;
    float c01 = s[p01 + w0]; c01 += (s[p01 + w1] - c01) * ww;
    float c10 = s[p10 + w0]; c10 += (s[p10 + w1] - c10) * ww;
    float c11 = s[p11 + w0]; c11 += (s[p11 + w1] - c11) * ww;
    float c0 = c00 + (c01 - c00) * wh;
    float c1 = c10 + (c11 - c10) * wh;
    return c0 + (c1 - c0) * wt;
}

__global__ void k_final(const float* __restrict__ xc, float* __restrict__ out) {
    int idx = blockIdx.x * 256 + threadIdx.x;
    int w = idx % WF;
    int h = (idx / WF) % HF;
    int t = (idx / (WF * HF)) % TF;
    int bc = idx / (WF * HF * TF);

    float pt = (float)t * (7.0f / 15.0f);
    int t0 = (int)pt; float wt = pt - (float)t0; int t1 = min(t0 + 1, 7); t0 = min(t0, 7);
    float ph = (float)h * (23.0f / 47.0f);
    int h0 = (int)ph; float wh = ph - (float)h0; int h1 = min(h0 + 1, 23); h0 = min(h0, 23);
    float pw = (float)w * (23.0f / 47.0f);
    int w0 = (int)pw; float ww = pw - (float)w0; int w1 = min(w0 + 1, 23); w0 = min(w0, 23);

    int base = bc * NP;
    int p00 = t0 * (HHd * WWd) + h0 * WWd;
    int p01 = t0 * (HHd * WWd) + h1 * WWd;
    int p10 = t1 * (HHd * WWd) + h0 * WWd;
    int p11 = t1 * (HHd * WWd) + h1 * WWd;

    float r_cross = tri8(g_up[0] + base, p00, p01, p10, p11, w0, w1, ww, wh, wt);
    float r_self  = tri8(g_up[1] + base, p00, p01, p10, p11, w0, w1, ww, wh, wt);
    out[idx] = r_self + xc[idx] - 0.5f * r_cross;
}

// ---------------- launch ----------------
extern "C" void kernel_launch(void* const* d_in, const int* in_sizes, int n_in,
                              void* d_out, int out_size) {
    const float* x       = (const float*)d_in[0];
    const float* x_c     = (const float*)d_in[1];
    const float* w_down  = (const float*)d_in[2];
    const float* b_down  = (const float*)d_in[3];
    const float* w_downc = (const float*)d_in[4];
    const float* b_downc = (const float*)d_in[5];
    const float* w_q     = (const float*)d_in[6];
    const float* b_q     = (const float*)d_in[7];
    const float* w_k     = (const float*)d_in[8];
    const float* b_k     = (const float*)d_in[9];
    const float* w_v     = (const float*)d_in[10];
    const float* b_v     = (const float*)d_in[11];
    const float* w_qsa   = (const float*)d_in[12];
    const float* b_qsa   = (const float*)d_in[13];
    const float* w_ksa   = (const float*)d_in[14];
    const float* b_ksa   = (const float*)d_in[15];
    const float* w_vsa   = (const float*)d_in[16];
    const float* b_vsa   = (const float*)d_in[17];
    const float* gn_w    = (const float*)d_in[18];
    const float* gn_b    = (const float*)d_in[19];
    const float* gn_wsa  = (const float*)d_in[20];
    const float* gn_bsa  = (const float*)d_in[21];
    const float* w_up    = (const float*)d_in[22];
    const float* b_up    = (const float*)d_in[23];
    const float* w_upsa  = (const float*)d_in[24];
    const float* b_upsa  = (const float*)d_in[25];
    const float* offset  = (const float*)d_in[26];
    const float* offsetc = (const float*)d_in[27];

    dim3 g1(2304, 1, 2);
    k_resize<<<g1, 256>>>(x, x_c);

    dim3 g2(72, 1, 2);
    k_down<<<g2, 128>>>(w_down, b_down, w_downc, b_downc);

    dim3 g3(72, 1, 2);
    k_proj<<<g3, 128>>>(w_q, b_q, w_k, b_k, w_v, b_v,
                        w_qsa, b_qsa, w_ksa, b_ksa, w_vsa, b_vsa,
                        offset, offsetc);

    dim3 g4(72, NB, 2);
    k_attn<<<g4, 128>>>();

    k_stats<<<32, 256>>>();

    dim3 g6(36, NB, 2);
    k_gnup<<<g6, 128>>>(gn_w, gn_b, gn_wsa, gn_bsa, w_up, b_up, w_upsa, b_upsa);

    k_final<<<18432, 256>>>(x_c, (float*)d_out);
}